// round 1
// baseline (speedup 1.0000x reference)
#include <cuda_runtime.h>
#include <math.h>

#define BB 4
#define CHN 256
#define HH 64
#define WW 64
#define HW (HH*WW)        // 4096
#define NP (BB*HW)        // 16384 pixels
#define K9 9
#define KD (CHN*K9)       // 2304

// ---------------- scratch (device globals: allocation-free) ----------------
__device__ float g_act0[NP*CHN];          // NHWC activations ping (16 MB)
__device__ float g_act1[NP*CHN];          // pong
__device__ float g_om[NP*27];             // offset-conv output [p][27]
__device__ float g_col[(size_t)NP*KD];    // im2col of deformed samples (151 MB)
__device__ float g_wt[KD*CHN];            // main weight transposed [k*256+c][o]
__device__ float g_wofft[27*KD];          // offset weight transposed [kk][c][j]

// ---------------- generic 2D transpose (per-batch via grid.z) --------------
__global__ void transpose2d(const float* __restrict__ in, float* __restrict__ out,
                            int rows, int cols) {
    __shared__ float tile[32][33];
    int z = blockIdx.z;
    const float* ip = in + (size_t)z * rows * cols;
    float* op = out + (size_t)z * rows * cols;
    int c0 = blockIdx.x * 32, r0 = blockIdx.y * 32;
    int x = c0 + threadIdx.x;
    for (int i = threadIdx.y; i < 32; i += 8) {
        int r = r0 + i;
        tile[i][threadIdx.x] = (r < rows && x < cols) ? ip[(size_t)r*cols + x] : 0.f;
    }
    __syncthreads();
    int xo = r0 + threadIdx.x;
    for (int i = threadIdx.y; i < 32; i += 8) {
        int c = c0 + i;
        if (c < cols && xo < rows) op[(size_t)c*rows + xo] = tile[threadIdx.x][i];
    }
}

// ---------------- weight re-layouts ----------------------------------------
// g_wofft[((kk*256)+c)*27 + j] = woff[(j*256+c)*9 + kk]
__global__ void woff_trans_k(const float* __restrict__ woff) {
    int i = blockIdx.x * 256 + threadIdx.x;
    if (i >= 27*KD) return;
    int j = i % 27; int t = i / 27;
    int c = t & 255; int kk = t >> 8;
    g_wofft[i] = woff[(j*CHN + c)*9 + kk];
}

// g_wt[(kk*256+c)*256 + o] = w[(o*256+c)*9 + kk]
__global__ void wmain_trans_k(const float* __restrict__ w) {
    int i = blockIdx.x * 256 + threadIdx.x;
    if (i >= KD*CHN) return;
    int o = i & 255; int t = i >> 8;
    int c = t & 255; int kk = t >> 8;
    g_wt[i] = w[((size_t)(o*CHN + c))*9 + kk];
}

// ---------------- offset conv (NHWC, 3x3, pad 1, 27 outputs) ---------------
// block = 8 pixels along w of one row; stages 3x10x256 input patch in SMEM
__global__ __launch_bounds__(256) void offset_conv_k(const float* __restrict__ xh,
                                                     const float* __restrict__ boff) {
    __shared__ float sX[3*10*CHN];   // 30 KB
    __shared__ float sW[64*27];      // 6.75 KB, layout [cc][j]
    int b = blockIdx.z, h = blockIdx.y, w0 = blockIdx.x * 8;
    int tid = threadIdx.x;

    // cooperative load of neighborhood (zero-padded)
    for (int e4 = tid; e4 < 3*10*(CHN/4); e4 += 256) {
        int c4 = e4 & 63; int pos = e4 >> 6;
        int r = pos / 10, cc = pos % 10;
        int hy = h - 1 + r, wx = w0 - 1 + cc;
        float4 v = make_float4(0.f, 0.f, 0.f, 0.f);
        if (hy >= 0 && hy < HH && wx >= 0 && wx < WW)
            v = *(const float4*)(xh + ((size_t)((b*HH + hy)*WW + wx))*CHN + c4*4);
        ((float4*)sX)[e4] = v;
    }

    int item = tid;                 // 8 px * 27 j = 216 items
    int px = item / 27, j = item - px*27;
    bool active = item < 216;
    float acc = 0.f;

    for (int kk = 0; kk < 9; kk++) {
        int r = kk / 3, s = kk - r*3;
        for (int c0 = 0; c0 < CHN; c0 += 64) {
            __syncthreads();
            // stage contiguous weight chunk: g_wofft[(kk*256+c0)*27 .. +1728)
            for (int e = tid; e < 64*27; e += 256)
                sW[e] = g_wofft[(kk*CHN + c0)*27 + e];
            __syncthreads();
            if (active) {
                const float* xp = sX + (r*10 + px + s)*CHN + c0;
                #pragma unroll 8
                for (int cc = 0; cc < 64; cc++)
                    acc = fmaf(xp[cc], sW[cc*27 + j], acc);
            }
        }
    }
    if (active)
        g_om[((size_t)((b*HH + h)*WW + w0 + px))*27 + j] = acc + boff[j];
}

// ---------------- bilinear sample + mask -> im2col -------------------------
// one warp per (pixel, tap); each lane handles 8 channels via 2x float4
__global__ __launch_bounds__(256) void sample_k(const float* __restrict__ xh) {
    int wid = blockIdx.x * 8 + (threadIdx.x >> 5);   // < NP*9
    int lane = threadIdx.x & 31;
    int p = wid / 9, k = wid - p*9;
    const float* omp = g_om + (size_t)p * 27;
    float dy = omp[2*k], dx = omp[2*k + 1];
    float mk = 1.f / (1.f + __expf(-omp[18 + k]));
    int b = p >> 12, hw = p & (HW - 1), h = hw >> 6, w = hw & 63;
    float ys = (float)(h + k/3 - 1) + dy;
    float xs = (float)(w + k%3 - 1) + dx;
    float y0f = floorf(ys), x0f = floorf(xs);
    float wy = ys - y0f, wx = xs - x0f;
    int y0 = (int)y0f, x0 = (int)x0f;
    int y1 = y0 + 1, x1 = x0 + 1;
    bool vy0 = ((unsigned)y0 < HH), vy1 = ((unsigned)y1 < HH);
    bool vx0 = ((unsigned)x0 < WW), vx1 = ((unsigned)x1 < WW);
    float w00 = (1.f - wy)*(1.f - wx)*mk;
    float w01 = (1.f - wy)*wx*mk;
    float w10 = wy*(1.f - wx)*mk;
    float w11 = wy*wx*mk;
    const float* base = xh + (size_t)b * HW * CHN;
    int c0 = lane * 8;
    const float4 z4 = make_float4(0.f, 0.f, 0.f, 0.f);
    float4 a00 = z4, b00 = z4, a01 = z4, b01 = z4;
    float4 a10 = z4, b10 = z4, a11 = z4, b11 = z4;
    if (vy0 && vx0) { const float4* q = (const float4*)(base + (size_t)(y0*WW + x0)*CHN + c0); a00 = q[0]; b00 = q[1]; }
    if (vy0 && vx1) { const float4* q = (const float4*)(base + (size_t)(y0*WW + x1)*CHN + c0); a01 = q[0]; b01 = q[1]; }
    if (vy1 && vx0) { const float4* q = (const float4*)(base + (size_t)(y1*WW + x0)*CHN + c0); a10 = q[0]; b10 = q[1]; }
    if (vy1 && vx1) { const float4* q = (const float4*)(base + (size_t)(y1*WW + x1)*CHN + c0); a11 = q[0]; b11 = q[1]; }
    float4 o0, o1;
    o0.x = w00*a00.x + w01*a01.x + w10*a10.x + w11*a11.x;
    o0.y = w00*a00.y + w01*a01.y + w10*a10.y + w11*a11.y;
    o0.z = w00*a00.z + w01*a01.z + w10*a10.z + w11*a11.z;
    o0.w = w00*a00.w + w01*a01.w + w10*a10.w + w11*a11.w;
    o1.x = w00*b00.x + w01*b01.x + w10*b10.x + w11*b11.x;
    o1.y = w00*b00.y + w01*b01.y + w10*b10.y + w11*b11.y;
    o1.z = w00*b00.z + w01*b01.z + w10*b10.z + w11*b11.z;
    o1.w = w00*b00.w + w01*b01.w + w10*b10.w + w11*b11.w;
    float4* dst = (float4*)(g_col + (size_t)wid*CHN + c0);
    dst[0] = o0; dst[1] = o1;
}

// ---------------- GEMM: [16384 x 2304] @ [2304 x 256] + bias + ReLU --------
#define BM 128
#define BN 64
#define BKK 16
__global__ __launch_bounds__(128) void gemm_k(const float* __restrict__ bias,
                                              float* __restrict__ Cout) {
    __shared__ float As[2][BKK][BM];   // 16 KB
    __shared__ float Bs[2][BKK][BN];   // 8 KB
    int tid = threadIdx.x;
    int m0 = blockIdx.x * BM;
    int n0 = blockIdx.y * BN;
    int tx = tid & 7, ty = tid >> 3;

    const float* aRow = g_col + (size_t)(m0 + tid) * KD;
    int bk_r = tid >> 3;            // B-tile row 0..15
    int bn_c = (tid & 7) * 8;       // B-tile col

    float4 a4[4]; float4 b4[2];
    // prologue: tile 0
    #pragma unroll
    for (int q = 0; q < 4; q++) a4[q] = *(const float4*)(aRow + q*4);
    {
        const float* bp = g_wt + (size_t)bk_r * CHN + n0 + bn_c;
        b4[0] = *(const float4*)bp;
        b4[1] = *(const float4*)(bp + 4);
    }
    #pragma unroll
    for (int q = 0; q < 4; q++) {
        As[0][q*4+0][tid] = a4[q].x; As[0][q*4+1][tid] = a4[q].y;
        As[0][q*4+2][tid] = a4[q].z; As[0][q*4+3][tid] = a4[q].w;
    }
    *(float4*)&Bs[0][bk_r][bn_c]   = b4[0];
    *(float4*)&Bs[0][bk_r][bn_c+4] = b4[1];
    __syncthreads();

    float acc[8][8] = {};
    const int NT = KD / BKK;   // 144
    for (int kt = 0; kt < NT; kt++) {
        int cur = kt & 1;
        if (kt + 1 < NT) {
            const float* ap = aRow + (kt + 1) * BKK;
            #pragma unroll
            for (int q = 0; q < 4; q++) a4[q] = *(const float4*)(ap + q*4);
            const float* bp = g_wt + (size_t)((kt + 1)*BKK + bk_r) * CHN + n0 + bn_c;
            b4[0] = *(const float4*)bp;
            b4[1] = *(const float4*)(bp + 4);
        }
        #pragma unroll
        for (int kk = 0; kk < BKK; kk++) {
            float ar[8], br[8];
            #pragma unroll
            for (int i = 0; i < 8; i++) ar[i] = As[cur][kk][ty*8 + i];
            #pragma unroll
            for (int j = 0; j < 8; j++) br[j] = Bs[cur][kk][tx*8 + j];
            #pragma unroll
            for (int i = 0; i < 8; i++)
                #pragma unroll
                for (int j = 0; j < 8; j++)
                    acc[i][j] = fmaf(ar[i], br[j], acc[i][j]);
        }
        if (kt + 1 < NT) {
            int nxt = cur ^ 1;
            #pragma unroll
            for (int q = 0; q < 4; q++) {
                As[nxt][q*4+0][tid] = a4[q].x; As[nxt][q*4+1][tid] = a4[q].y;
                As[nxt][q*4+2][tid] = a4[q].z; As[nxt][q*4+3][tid] = a4[q].w;
            }
            *(float4*)&Bs[nxt][bk_r][bn_c]   = b4[0];
            *(float4*)&Bs[nxt][bk_r][bn_c+4] = b4[1];
        }
        __syncthreads();
    }

    float bv[8];
    #pragma unroll
    for (int j = 0; j < 8; j++) bv[j] = bias[n0 + tx*8 + j];
    #pragma unroll
    for (int i = 0; i < 8; i++) {
        int m = m0 + ty*8 + i;
        float4 o0, o1;
        o0.x = fmaxf(acc[i][0] + bv[0], 0.f);
        o0.y = fmaxf(acc[i][1] + bv[1], 0.f);
        o0.z = fmaxf(acc[i][2] + bv[2], 0.f);
        o0.w = fmaxf(acc[i][3] + bv[3], 0.f);
        o1.x = fmaxf(acc[i][4] + bv[4], 0.f);
        o1.y = fmaxf(acc[i][5] + bv[5], 0.f);
        o1.z = fmaxf(acc[i][6] + bv[6], 0.f);
        o1.w = fmaxf(acc[i][7] + bv[7], 0.f);
        *(float4*)(Cout + (size_t)m*CHN + n0 + tx*8)     = o0;
        *(float4*)(Cout + (size_t)m*CHN + n0 + tx*8 + 4) = o1;
    }
}

// ---------------- launcher ---------------------------------------------------
extern "C" void kernel_launch(void* const* d_in, const int* in_sizes, int n_in,
                              void* d_out, int out_size) {
    const float* x = (const float*)d_in[0];
    const float* woff[3] = {(const float*)d_in[1], (const float*)d_in[5], (const float*)d_in[9]};
    const float* boff[3] = {(const float*)d_in[2], (const float*)d_in[6], (const float*)d_in[10]};
    const float* wm[3]   = {(const float*)d_in[3], (const float*)d_in[7], (const float*)d_in[11]};
    const float* bm[3]   = {(const float*)d_in[4], (const float*)d_in[8], (const float*)d_in[12]};
    float* out = (float*)d_out;

    float *act0, *act1;
    cudaGetSymbolAddress((void**)&act0, g_act0);
    cudaGetSymbolAddress((void**)&act1, g_act1);
    float* bufs[2] = {act0, act1};

    dim3 tb(32, 8);
    // x NCHW -> NHWC
    transpose2d<<<dim3(HW/32, CHN/32, BB), tb>>>(x, act0, CHN, HW);

    for (int L = 0; L < 3; L++) {
        const float* src = bufs[L & 1];
        float* dst = bufs[(L & 1) ^ 1];
        woff_trans_k<<<(27*KD + 255)/256, 256>>>(woff[L]);
        wmain_trans_k<<<(KD*CHN + 255)/256, 256>>>(wm[L]);
        offset_conv_k<<<dim3(WW/8, HH, BB), 256>>>(src, boff[L]);
        sample_k<<<(NP*9)/8, 256>>>(src);
        gemm_k<<<dim3(NP/BM, CHN/BN), 128>>>(bm[L], dst);
    }

    // NHWC -> NCHW into d_out
    transpose2d<<<dim3(CHN/32, HW/32, BB), tb>>>(bufs[1], out, HW, CHN);
}

// round 2
// speedup vs baseline: 1.0497x; 1.0497x over previous
#include <cuda_runtime.h>
#include <math.h>
#include <stdint.h>

#define BB 4
#define CHN 256
#define HH 64
#define WW 64
#define HW (HH*WW)        // 4096
#define NP (BB*HW)        // 16384 pixels
#define K9 9
#define KD (CHN*K9)       // 2304

// ---------------- scratch (device globals: allocation-free) ----------------
__device__ float g_act0[NP*CHN];          // NHWC activations ping (16 MB)
__device__ float g_act1[NP*CHN];          // pong
__device__ float g_om[NP*27];             // offset-conv output [p][27]
__device__ float g_col[(size_t)NP*KD];    // im2col of deformed samples (151 MB)
__device__ float g_wt[KD*CHN];            // main weight transposed [k*256+c][o]
__device__ float g_woffp[KD*32];          // offset weight [kk*256+c][32] (27 used, padded)

// ---------------- packed f32x2 helpers --------------------------------------
__device__ __forceinline__ uint64_t fma2(uint64_t a, uint64_t b, uint64_t c) {
    uint64_t d;
    asm("fma.rn.f32x2 %0, %1, %2, %3;" : "=l"(d) : "l"(a), "l"(b), "l"(c));
    return d;
}
__device__ __forceinline__ uint64_t splat2(float v) {
    uint64_t d;
    asm("mov.b64 %0, {%1, %1};" : "=l"(d) : "f"(v));
    return d;
}
__device__ __forceinline__ void unpack2(uint64_t v, float& lo, float& hi) {
    asm("mov.b64 {%0, %1}, %2;" : "=f"(lo), "=f"(hi) : "l"(v));
}

// ---------------- generic 2D transpose (per-batch via grid.z) --------------
__global__ void transpose2d(const float* __restrict__ in, float* __restrict__ out,
                            int rows, int cols) {
    __shared__ float tile[32][33];
    int z = blockIdx.z;
    const float* ip = in + (size_t)z * rows * cols;
    float* op = out + (size_t)z * rows * cols;
    int c0 = blockIdx.x * 32, r0 = blockIdx.y * 32;
    int x = c0 + threadIdx.x;
    for (int i = threadIdx.y; i < 32; i += 8) {
        int r = r0 + i;
        tile[i][threadIdx.x] = (r < rows && x < cols) ? ip[(size_t)r*cols + x] : 0.f;
    }
    __syncthreads();
    int xo = r0 + threadIdx.x;
    for (int i = threadIdx.y; i < 32; i += 8) {
        int c = c0 + i;
        if (c < cols && xo < rows) op[(size_t)c*rows + xo] = tile[threadIdx.x][i];
    }
}

// ---------------- weight re-layouts ----------------------------------------
// g_woffp[(kk*256+c)*32 + j] = woff[(j*256+c)*9 + kk]  (j<27; else 0)
__global__ void woff_trans_k(const float* __restrict__ woff) {
    int i = blockIdx.x * 256 + threadIdx.x;
    if (i >= KD*32) return;
    int j = i & 31; int t = i >> 5;
    int c = t & 255; int kk = t >> 8;
    g_woffp[i] = (j < 27) ? woff[(j*CHN + c)*9 + kk] : 0.f;
}

// g_wt[(kk*256+c)*256 + o] = w[(o*256+c)*9 + kk]
__global__ void wmain_trans_k(const float* __restrict__ w) {
    int i = blockIdx.x * 256 + threadIdx.x;
    if (i >= KD*CHN) return;
    int o = i & 255; int t = i >> 8;
    int c = t & 255; int kk = t >> 8;
    g_wt[i] = w[((size_t)(o*CHN + c))*9 + kk];
}

// ---------------- offset conv: implicit GEMM -------------------------------
// M = 16384 pixels, N = 32 (27 padded), K = 2304. Block = 128 px (2 rows) x 32 j.
// 256 threads; A tiles gathered from NHWC x with the tap shift; f32x2 FMAs.
__global__ __launch_bounds__(256) void offset_conv_g(const float* __restrict__ xh,
                                                     const float* __restrict__ boff) {
    __shared__ __align__(16) float As[16][128];
    __shared__ __align__(16) float Bs[16][32];
    int bid = blockIdx.x;               // 128 blocks
    int b = bid >> 5, h0 = (bid & 31) * 2;
    int t = threadIdx.x;

    // staging roles: thread handles pixel m_ld, c-half chalf (8 channels)
    int m_ld = t & 127, chalf = t >> 7;
    int row_ld = m_ld >> 6, w_ld = m_ld & 63;

    // compute roles: ty -> 4 pixels, tx -> 4 j outputs
    int ty = t >> 3, tx = t & 7;        // ty 0..31, tx 0..7 -> j = tx*4..tx*4+3

    uint64_t acc2[2][4];
    #pragma unroll
    for (int i = 0; i < 2; i++)
        #pragma unroll
        for (int j = 0; j < 4; j++) acc2[i][j] = 0ull;

    for (int kt = 0; kt < 144; kt++) {
        int kk = kt >> 4, c0 = (kt & 15) << 4;
        int r = kk / 3, s = kk - r*3;
        // prefetch A chunk (global) for this tile
        int hy = h0 + row_ld + r - 1;
        int wx = w_ld + s - 1;
        bool v = ((unsigned)hy < (unsigned)HH) && ((unsigned)wx < (unsigned)WW);
        float4 q0 = make_float4(0,0,0,0), q1 = q0;
        if (v) {
            const float4* src = (const float4*)(xh + ((size_t)((b*HH + hy)*WW + wx))*CHN + c0 + chalf*8);
            q0 = src[0]; q1 = src[1];
        }
        // prefetch B chunk (2 contiguous floats per thread; padded layout)
        int e = t * 2;                   // 0..511 ; c = e>>5, j = e&31
        float2 bw = *(const float2*)(g_woffp + ((size_t)((kk << 8) + c0 + (e >> 5)) << 5) + (e & 31));

        __syncthreads();                 // previous tile's compute done
        int cb = chalf * 8;
        As[cb+0][m_ld] = q0.x; As[cb+1][m_ld] = q0.y;
        As[cb+2][m_ld] = q0.z; As[cb+3][m_ld] = q0.w;
        As[cb+4][m_ld] = q1.x; As[cb+5][m_ld] = q1.y;
        As[cb+6][m_ld] = q1.z; As[cb+7][m_ld] = q1.w;
        *(float2*)&Bs[e >> 5][e & 31] = bw;
        __syncthreads();

        #pragma unroll
        for (int ck = 0; ck < 16; ck++) {
            uint64_t ar2[2];
            ar2[0] = *(const uint64_t*)&As[ck][ty*4 + 0];
            ar2[1] = *(const uint64_t*)&As[ck][ty*4 + 2];
            float4 b4 = *(const float4*)&Bs[ck][tx*4];
            uint64_t br2[4];
            br2[0] = splat2(b4.x); br2[1] = splat2(b4.y);
            br2[2] = splat2(b4.z); br2[3] = splat2(b4.w);
            #pragma unroll
            for (int i = 0; i < 2; i++)
                #pragma unroll
                for (int j = 0; j < 4; j++)
                    acc2[i][j] = fma2(ar2[i], br2[j], acc2[i][j]);
        }
    }

    // epilogue: write g_om[p][27] (+bias), skip padded j>=27
    #pragma unroll
    for (int i2 = 0; i2 < 2; i2++) {
        int m0 = ty*4 + 2*i2;
        #pragma unroll
        for (int jj = 0; jj < 4; jj++) {
            int j = tx*4 + jj;
            if (j >= 27) continue;
            float lo, hi;
            unpack2(acc2[i2][jj], lo, hi);
            float bv = boff[j];
            int m = m0;
            int p = ((b*HH + h0 + (m >> 6))*WW + (m & 63));
            g_om[(size_t)p*27 + j] = lo + bv;
            m = m0 + 1;
            p = ((b*HH + h0 + (m >> 6))*WW + (m & 63));
            g_om[(size_t)p*27 + j] = hi + bv;
        }
    }
}

// ---------------- bilinear sample + mask -> im2col -------------------------
// one warp per (pixel, tap); each lane handles 8 channels via 2x float4
__global__ __launch_bounds__(256) void sample_k(const float* __restrict__ xh) {
    int wid = blockIdx.x * 8 + (threadIdx.x >> 5);   // < NP*9
    int lane = threadIdx.x & 31;
    int p = wid / 9, k = wid - p*9;
    const float* omp = g_om + (size_t)p * 27;
    float dy = omp[2*k], dx = omp[2*k + 1];
    float mk = 1.f / (1.f + __expf(-omp[18 + k]));
    int b = p >> 12, hw = p & (HW - 1), h = hw >> 6, w = hw & 63;
    float ys = (float)(h + k/3 - 1) + dy;
    float xs = (float)(w + k%3 - 1) + dx;
    float y0f = floorf(ys), x0f = floorf(xs);
    float wy = ys - y0f, wx = xs - x0f;
    int y0 = (int)y0f, x0 = (int)x0f;
    int y1 = y0 + 1, x1 = x0 + 1;
    bool vy0 = ((unsigned)y0 < HH), vy1 = ((unsigned)y1 < HH);
    bool vx0 = ((unsigned)x0 < WW), vx1 = ((unsigned)x1 < WW);
    float w00 = (1.f - wy)*(1.f - wx)*mk;
    float w01 = (1.f - wy)*wx*mk;
    float w10 = wy*(1.f - wx)*mk;
    float w11 = wy*wx*mk;
    const float* base = xh + (size_t)b * HW * CHN;
    int c0 = lane * 8;
    const float4 z4 = make_float4(0.f, 0.f, 0.f, 0.f);
    float4 a00 = z4, b00 = z4, a01 = z4, b01 = z4;
    float4 a10 = z4, b10 = z4, a11 = z4, b11 = z4;
    if (vy0 && vx0) { const float4* q = (const float4*)(base + (size_t)(y0*WW + x0)*CHN + c0); a00 = q[0]; b00 = q[1]; }
    if (vy0 && vx1) { const float4* q = (const float4*)(base + (size_t)(y0*WW + x1)*CHN + c0); a01 = q[0]; b01 = q[1]; }
    if (vy1 && vx0) { const float4* q = (const float4*)(base + (size_t)(y1*WW + x0)*CHN + c0); a10 = q[0]; b10 = q[1]; }
    if (vy1 && vx1) { const float4* q = (const float4*)(base + (size_t)(y1*WW + x1)*CHN + c0); a11 = q[0]; b11 = q[1]; }
    float4 o0, o1;
    o0.x = w00*a00.x + w01*a01.x + w10*a10.x + w11*a11.x;
    o0.y = w00*a00.y + w01*a01.y + w10*a10.y + w11*a11.y;
    o0.z = w00*a00.z + w01*a01.z + w10*a10.z + w11*a11.z;
    o0.w = w00*a00.w + w01*a01.w + w10*a10.w + w11*a11.w;
    o1.x = w00*b00.x + w01*b01.x + w10*b10.x + w11*b11.x;
    o1.y = w00*b00.y + w01*b01.y + w10*b10.y + w11*b11.y;
    o1.z = w00*b00.z + w01*b01.z + w10*b10.z + w11*b11.z;
    o1.w = w00*b00.w + w01*b01.w + w10*b10.w + w11*b11.w;
    float4* dst = (float4*)(g_col + (size_t)wid*CHN + c0);
    dst[0] = o0; dst[1] = o1;
}

// ---------------- GEMM: [16384 x 2304] @ [2304 x 256] + bias + ReLU --------
// 128 threads, BM=128, BN=64, BKK=16, double-buffered, f32x2 inner loop.
#define BM 128
#define BN 64
#define BKK 16
__global__ __launch_bounds__(128) void gemm_k(const float* __restrict__ bias,
                                              float* __restrict__ Cout) {
    __shared__ __align__(16) float As[2][BKK][BM];   // 16 KB
    __shared__ __align__(16) float Bs[2][BKK][BN];   // 8 KB
    int tid = threadIdx.x;
    int m0 = blockIdx.x * BM;
    int n0 = blockIdx.y * BN;
    int tx = tid & 7, ty = tid >> 3;

    const float* aRow = g_col + (size_t)(m0 + tid) * KD;
    int bk_r = tid >> 3;            // B-tile row 0..15
    int bn_c = (tid & 7) * 8;       // B-tile col

    float4 a4[4]; float4 b4[2];
    // prologue: tile 0
    #pragma unroll
    for (int q = 0; q < 4; q++) a4[q] = *(const float4*)(aRow + q*4);
    {
        const float* bp = g_wt + (size_t)bk_r * CHN + n0 + bn_c;
        b4[0] = *(const float4*)bp;
        b4[1] = *(const float4*)(bp + 4);
    }
    #pragma unroll
    for (int q = 0; q < 4; q++) {
        As[0][q*4+0][tid] = a4[q].x; As[0][q*4+1][tid] = a4[q].y;
        As[0][q*4+2][tid] = a4[q].z; As[0][q*4+3][tid] = a4[q].w;
    }
    *(float4*)&Bs[0][bk_r][bn_c]   = b4[0];
    *(float4*)&Bs[0][bk_r][bn_c+4] = b4[1];
    __syncthreads();

    uint64_t acc2[4][8];
    #pragma unroll
    for (int i = 0; i < 4; i++)
        #pragma unroll
        for (int j = 0; j < 8; j++) acc2[i][j] = 0ull;

    const int NT = KD / BKK;   // 144
    for (int kt = 0; kt < NT; kt++) {
        int cur = kt & 1;
        if (kt + 1 < NT) {
            const float* ap = aRow + (kt + 1) * BKK;
            #pragma unroll
            for (int q = 0; q < 4; q++) a4[q] = *(const float4*)(ap + q*4);
            const float* bp = g_wt + (size_t)((kt + 1)*BKK + bk_r) * CHN + n0 + bn_c;
            b4[0] = *(const float4*)bp;
            b4[1] = *(const float4*)(bp + 4);
        }
        #pragma unroll
        for (int kk = 0; kk < BKK; kk++) {
            uint64_t ar2[4];
            #pragma unroll
            for (int i2 = 0; i2 < 4; i2++)
                ar2[i2] = *(const uint64_t*)&As[cur][kk][ty*8 + 2*i2];
            float4 bA = *(const float4*)&Bs[cur][kk][tx*8];
            float4 bB = *(const float4*)&Bs[cur][kk][tx*8 + 4];
            uint64_t br2[8];
            br2[0] = splat2(bA.x); br2[1] = splat2(bA.y);
            br2[2] = splat2(bA.z); br2[3] = splat2(bA.w);
            br2[4] = splat2(bB.x); br2[5] = splat2(bB.y);
            br2[6] = splat2(bB.z); br2[7] = splat2(bB.w);
            #pragma unroll
            for (int i2 = 0; i2 < 4; i2++)
                #pragma unroll
                for (int j = 0; j < 8; j++)
                    acc2[i2][j] = fma2(ar2[i2], br2[j], acc2[i2][j]);
        }
        if (kt + 1 < NT) {
            int nxt = cur ^ 1;
            #pragma unroll
            for (int q = 0; q < 4; q++) {
                As[nxt][q*4+0][tid] = a4[q].x; As[nxt][q*4+1][tid] = a4[q].y;
                As[nxt][q*4+2][tid] = a4[q].z; As[nxt][q*4+3][tid] = a4[q].w;
            }
            *(float4*)&Bs[nxt][bk_r][bn_c]   = b4[0];
            *(float4*)&Bs[nxt][bk_r][bn_c+4] = b4[1];
        }
        __syncthreads();
    }

    float bv[8];
    #pragma unroll
    for (int j = 0; j < 8; j++) bv[j] = bias[n0 + tx*8 + j];
    #pragma unroll
    for (int i2 = 0; i2 < 4; i2++) {
        float r0[8], r1[8];
        #pragma unroll
        for (int j = 0; j < 8; j++) unpack2(acc2[i2][j], r0[j], r1[j]);
        int mA = m0 + ty*8 + 2*i2;
        float4 oA0, oA1, oB0, oB1;
        oA0.x = fmaxf(r0[0] + bv[0], 0.f); oA0.y = fmaxf(r0[1] + bv[1], 0.f);
        oA0.z = fmaxf(r0[2] + bv[2], 0.f); oA0.w = fmaxf(r0[3] + bv[3], 0.f);
        oA1.x = fmaxf(r0[4] + bv[4], 0.f); oA1.y = fmaxf(r0[5] + bv[5], 0.f);
        oA1.z = fmaxf(r0[6] + bv[6], 0.f); oA1.w = fmaxf(r0[7] + bv[7], 0.f);
        oB0.x = fmaxf(r1[0] + bv[0], 0.f); oB0.y = fmaxf(r1[1] + bv[1], 0.f);
        oB0.z = fmaxf(r1[2] + bv[2], 0.f); oB0.w = fmaxf(r1[3] + bv[3], 0.f);
        oB1.x = fmaxf(r1[4] + bv[4], 0.f); oB1.y = fmaxf(r1[5] + bv[5], 0.f);
        oB1.z = fmaxf(r1[6] + bv[6], 0.f); oB1.w = fmaxf(r1[7] + bv[7], 0.f);
        *(float4*)(Cout + (size_t)mA*CHN + n0 + tx*8)         = oA0;
        *(float4*)(Cout + (size_t)mA*CHN + n0 + tx*8 + 4)     = oA1;
        *(float4*)(Cout + (size_t)(mA+1)*CHN + n0 + tx*8)     = oB0;
        *(float4*)(Cout + (size_t)(mA+1)*CHN + n0 + tx*8 + 4) = oB1;
    }
}

// ---------------- launcher ---------------------------------------------------
extern "C" void kernel_launch(void* const* d_in, const int* in_sizes, int n_in,
                              void* d_out, int out_size) {
    const float* x = (const float*)d_in[0];
    const float* woff[3] = {(const float*)d_in[1], (const float*)d_in[5], (const float*)d_in[9]};
    const float* boff[3] = {(const float*)d_in[2], (const float*)d_in[6], (const float*)d_in[10]};
    const float* wm[3]   = {(const float*)d_in[3], (const float*)d_in[7], (const float*)d_in[11]};
    const float* bm[3]   = {(const float*)d_in[4], (const float*)d_in[8], (const float*)d_in[12]};
    float* out = (float*)d_out;

    float *act0, *act1;
    cudaGetSymbolAddress((void**)&act0, g_act0);
    cudaGetSymbolAddress((void**)&act1, g_act1);
    float* bufs[2] = {act0, act1};

    dim3 tb(32, 8);
    // x NCHW -> NHWC
    transpose2d<<<dim3(HW/32, CHN/32, BB), tb>>>(x, act0, CHN, HW);

    for (int L = 0; L < 3; L++) {
        const float* src = bufs[L & 1];
        float* dst = bufs[(L & 1) ^ 1];
        woff_trans_k<<<(KD*32 + 255)/256, 256>>>(woff[L]);
        wmain_trans_k<<<(KD*CHN + 255)/256, 256>>>(wm[L]);
        offset_conv_g<<<128, 256>>>(src, boff[L]);
        sample_k<<<(NP*9)/8, 256>>>(src);
        gemm_k<<<dim3(NP/BM, CHN/BN), 128>>>(bm[L], dst);
    }

    // NHWC -> NCHW into d_out
    transpose2d<<<dim3(CHN/32, HW/32, BB), tb>>>(bufs[1], out, HW, CHN);
}

// round 7
// speedup vs baseline: 2.0506x; 1.9535x over previous
#include <cuda_runtime.h>
#include <cuda_bf16.h>
#include <math.h>
#include <stdint.h>

#define BB 4
#define CHN 256
#define HH 64
#define WW 64
#define HW (HH*WW)        // 4096
#define NP (BB*HW)        // 16384 pixels
#define K9 9
#define KD (CHN*K9)       // 2304

// ---------------- scratch (device globals: allocation-free) ----------------
__device__ float g_act0[NP*CHN];                 // NHWC activations ping (16 MB)
__device__ float g_act1[NP*CHN];                 // pong
__device__ float g_om[NP*27];                    // offset-conv output [p][27]
__device__ uint16_t g_colh[(size_t)NP*KD];       // im2col bf16 hi (75.5 MB)
__device__ uint16_t g_coll[(size_t)NP*KD];       // im2col bf16 lo
__device__ uint16_t g_wtBh[CHN*KD];              // weight B[o][k] bf16 hi
__device__ uint16_t g_wtBl[CHN*KD];              // weight B[o][k] bf16 lo
__device__ float g_woffp[KD*32];                 // offset weight [kk*256+c][32]

// ---------------- helpers ----------------------------------------------------
__device__ __forceinline__ uint64_t fma2(uint64_t a, uint64_t b, uint64_t c) {
    uint64_t d;
    asm("fma.rn.f32x2 %0, %1, %2, %3;" : "=l"(d) : "l"(a), "l"(b), "l"(c));
    return d;
}
__device__ __forceinline__ uint64_t splat2(float v) {
    uint64_t d;
    asm("mov.b64 %0, {%1, %1};" : "=l"(d) : "f"(v));
    return d;
}
__device__ __forceinline__ void unpack2(uint64_t v, float& lo, float& hi) {
    asm("mov.b64 {%0, %1}, %2;" : "=f"(lo), "=f"(hi) : "l"(v));
}
__device__ __forceinline__ uint32_t smem_u32(const void* p) {
    uint32_t a;
    asm("{ .reg .u64 t; cvta.to.shared.u64 t, %1; cvt.u32.u64 %0, t; }" : "=r"(a) : "l"(p));
    return a;
}
__device__ __forceinline__ uint16_t f2bf(float v) {
    __nv_bfloat16 b = __float2bfloat16(v);
    return *reinterpret_cast<uint16_t*>(&b);
}
__device__ __forceinline__ float bf2f(uint16_t u) {
    __nv_bfloat16 b = *reinterpret_cast<__nv_bfloat16*>(&u);
    return __bfloat162float(b);
}
// split f32 into bf16 hi + bf16 lo
__device__ __forceinline__ void bf_split(float v, uint16_t& h, uint16_t& l) {
    h = f2bf(v);
    float r = v - bf2f(h);
    l = f2bf(r);
}

#define LDSM4(r0, r1, r2, r3, addr) \
    asm volatile("ldmatrix.sync.aligned.m8n8.x4.shared.b16 {%0,%1,%2,%3}, [%4];" \
        : "=r"(r0), "=r"(r1), "=r"(r2), "=r"(r3) : "r"(addr))

#define MMA_BF16(d, a, b) \
    asm volatile("mma.sync.aligned.m16n8k16.row.col.f32.bf16.bf16.f32 " \
        "{%0,%1,%2,%3}, {%4,%5,%6,%7}, {%8,%9}, {%0,%1,%2,%3};" \
        : "+f"((d)[0]), "+f"((d)[1]), "+f"((d)[2]), "+f"((d)[3]) \
        : "r"((a)[0]), "r"((a)[1]), "r"((a)[2]), "r"((a)[3]), "r"((b)[0]), "r"((b)[1]))

// ---------------- generic 2D transpose (per-batch via grid.z) --------------
__global__ void transpose2d(const float* __restrict__ in, float* __restrict__ out,
                            int rows, int cols) {
    __shared__ float tile[32][33];
    int z = blockIdx.z;
    const float* ip = in + (size_t)z * rows * cols;
    float* op = out + (size_t)z * rows * cols;
    int c0 = blockIdx.x * 32, r0 = blockIdx.y * 32;
    int x = c0 + threadIdx.x;
    for (int i = threadIdx.y; i < 32; i += 8) {
        int r = r0 + i;
        tile[i][threadIdx.x] = (r < rows && x < cols) ? ip[(size_t)r*cols + x] : 0.f;
    }
    __syncthreads();
    int xo = r0 + threadIdx.x;
    for (int i = threadIdx.y; i < 32; i += 8) {
        int c = c0 + i;
        if (c < cols && xo < rows) op[(size_t)c*rows + xo] = tile[threadIdx.x][i];
    }
}

// ---------------- weight re-layouts ----------------------------------------
__global__ void woff_trans_k(const float* __restrict__ woff) {
    int i = blockIdx.x * 256 + threadIdx.x;
    if (i >= KD*32) return;
    int j = i & 31; int t = i >> 5;
    int c = t & 255; int kk = t >> 8;
    g_woffp[i] = (j < 27) ? woff[(j*CHN + c)*9 + kk] : 0.f;
}

// g_wtBh/l[o*KD + kk*256 + c] = bf16 split of w[(o*256+c)*9 + kk]
__global__ void wmain_trans_k(const float* __restrict__ w) {
    int i = blockIdx.x * 256 + threadIdx.x;
    if (i >= CHN*KD) return;
    int o = i / KD; int r = i - o*KD;
    int kk = r >> 8; int c = r & 255;
    float v = w[((size_t)(o*CHN + c))*9 + kk];
    uint16_t h, l;
    bf_split(v, h, l);
    g_wtBh[i] = h; g_wtBl[i] = l;
}

// ---------------- offset conv: implicit GEMM (f32x2) -----------------------
__global__ __launch_bounds__(256) void offset_conv_g(const float* __restrict__ xh,
                                                     const float* __restrict__ boff) {
    __shared__ __align__(16) float As[16][128];
    __shared__ __align__(16) float Bs[16][32];
    int bid = blockIdx.x;               // 128 blocks
    int b = bid >> 5, h0 = (bid & 31) * 2;
    int t = threadIdx.x;

    int m_ld = t & 127, chalf = t >> 7;
    int row_ld = m_ld >> 6, w_ld = m_ld & 63;
    int ty = t >> 3, tx = t & 7;

    uint64_t acc2[2][4];
    #pragma unroll
    for (int i = 0; i < 2; i++)
        #pragma unroll
        for (int j = 0; j < 4; j++) acc2[i][j] = 0ull;

    for (int kt = 0; kt < 144; kt++) {
        int kk = kt >> 4, c0 = (kt & 15) << 4;
        int r = kk / 3, s = kk - r*3;
        int hy = h0 + row_ld + r - 1;
        int wx = w_ld + s - 1;
        bool v = ((unsigned)hy < (unsigned)HH) && ((unsigned)wx < (unsigned)WW);
        float4 q0 = make_float4(0,0,0,0), q1 = q0;
        if (v) {
            const float4* src = (const float4*)(xh + ((size_t)((b*HH + hy)*WW + wx))*CHN + c0 + chalf*8);
            q0 = src[0]; q1 = src[1];
        }
        int e = t * 2;
        float2 bw = *(const float2*)(g_woffp + ((size_t)((kk << 8) + c0 + (e >> 5)) << 5) + (e & 31));

        __syncthreads();
        int cb = chalf * 8;
        As[cb+0][m_ld] = q0.x; As[cb+1][m_ld] = q0.y;
        As[cb+2][m_ld] = q0.z; As[cb+3][m_ld] = q0.w;
        As[cb+4][m_ld] = q1.x; As[cb+5][m_ld] = q1.y;
        As[cb+6][m_ld] = q1.z; As[cb+7][m_ld] = q1.w;
        *(float2*)&Bs[e >> 5][e & 31] = bw;
        __syncthreads();

        #pragma unroll
        for (int ck = 0; ck < 16; ck++) {
            uint64_t ar2[2];
            ar2[0] = *(const uint64_t*)&As[ck][ty*4 + 0];
            ar2[1] = *(const uint64_t*)&As[ck][ty*4 + 2];
            float4 b4 = *(const float4*)&Bs[ck][tx*4];
            uint64_t br2[4];
            br2[0] = splat2(b4.x); br2[1] = splat2(b4.y);
            br2[2] = splat2(b4.z); br2[3] = splat2(b4.w);
            #pragma unroll
            for (int i = 0; i < 2; i++)
                #pragma unroll
                for (int j = 0; j < 4; j++)
                    acc2[i][j] = fma2(ar2[i], br2[j], acc2[i][j]);
        }
    }

    #pragma unroll
    for (int i2 = 0; i2 < 2; i2++) {
        int m0 = ty*4 + 2*i2;
        #pragma unroll
        for (int jj = 0; jj < 4; jj++) {
            int j = tx*4 + jj;
            if (j >= 27) continue;
            float lo, hi;
            unpack2(acc2[i2][jj], lo, hi);
            float bv = boff[j];
            int m = m0;
            int p = ((b*HH + h0 + (m >> 6))*WW + (m & 63));
            g_om[(size_t)p*27 + j] = lo + bv;
            m = m0 + 1;
            p = ((b*HH + h0 + (m >> 6))*WW + (m & 63));
            g_om[(size_t)p*27 + j] = hi + bv;
        }
    }
}

// ---------------- bilinear sample + mask -> bf16 hi/lo im2col --------------
__global__ __launch_bounds__(256) void sample_k(const float* __restrict__ xh) {
    int wid = blockIdx.x * 8 + (threadIdx.x >> 5);
    int lane = threadIdx.x & 31;
    int p = wid / 9, k = wid - p*9;
    const float* omp = g_om + (size_t)p * 27;
    float dy = omp[2*k], dx = omp[2*k + 1];
    float mk = 1.f / (1.f + __expf(-omp[18 + k]));
    int b = p >> 12, hw = p & (HW - 1), h = hw >> 6, w = hw & 63;
    float ys = (float)(h + k/3 - 1) + dy;
    float xs = (float)(w + k%3 - 1) + dx;
    float y0f = floorf(ys), x0f = floorf(xs);
    float wy = ys - y0f, wx = xs - x0f;
    int y0 = (int)y0f, x0 = (int)x0f;
    int y1 = y0 + 1, x1 = x0 + 1;
    bool vy0 = ((unsigned)y0 < HH), vy1 = ((unsigned)y1 < HH);
    bool vx0 = ((unsigned)x0 < WW), vx1 = ((unsigned)x1 < WW);
    float w00 = (1.f - wy)*(1.f - wx)*mk;
    float w01 = (1.f - wy)*wx*mk;
    float w10 = wy*(1.f - wx)*mk;
    float w11 = wy*wx*mk;
    const float* base = xh + (size_t)b * HW * CHN;
    int c0 = lane * 8;
    const float4 z4 = make_float4(0.f, 0.f, 0.f, 0.f);
    float4 a00 = z4, b00 = z4, a01 = z4, b01 = z4;
    float4 a10 = z4, b10 = z4, a11 = z4, b11 = z4;
    if (vy0 && vx0) { const float4* q = (const float4*)(base + (size_t)(y0*WW + x0)*CHN + c0); a00 = q[0]; b00 = q[1]; }
    if (vy0 && vx1) { const float4* q = (const float4*)(base + (size_t)(y0*WW + x1)*CHN + c0); a01 = q[0]; b01 = q[1]; }
    if (vy1 && vx0) { const float4* q = (const float4*)(base + (size_t)(y1*WW + x0)*CHN + c0); a10 = q[0]; b10 = q[1]; }
    if (vy1 && vx1) { const float4* q = (const float4*)(base + (size_t)(y1*WW + x1)*CHN + c0); a11 = q[0]; b11 = q[1]; }
    float f[8];
    f[0] = w00*a00.x + w01*a01.x + w10*a10.x + w11*a11.x;
    f[1] = w00*a00.y + w01*a01.y + w10*a10.y + w11*a11.y;
    f[2] = w00*a00.z + w01*a01.z + w10*a10.z + w11*a11.z;
    f[3] = w00*a00.w + w01*a01.w + w10*a10.w + w11*a11.w;
    f[4] = w00*b00.x + w01*b01.x + w10*b10.x + w11*b11.x;
    f[5] = w00*b00.y + w01*b01.y + w10*b10.y + w11*b11.y;
    f[6] = w00*b00.z + w01*b01.z + w10*b10.z + w11*b11.z;
    f[7] = w00*b00.w + w01*b01.w + w10*b10.w + w11*b11.w;
    uint16_t hq[8], lq[8];
    #pragma unroll
    for (int q = 0; q < 8; q++) bf_split(f[q], hq[q], lq[q]);
    size_t idx = (size_t)wid*CHN + c0;
    uint4 hv, lv;
    hv.x = (uint32_t)hq[0] | ((uint32_t)hq[1] << 16);
    hv.y = (uint32_t)hq[2] | ((uint32_t)hq[3] << 16);
    hv.z = (uint32_t)hq[4] | ((uint32_t)hq[5] << 16);
    hv.w = (uint32_t)hq[6] | ((uint32_t)hq[7] << 16);
    lv.x = (uint32_t)lq[0] | ((uint32_t)lq[1] << 16);
    lv.y = (uint32_t)lq[2] | ((uint32_t)lq[3] << 16);
    lv.z = (uint32_t)lq[4] | ((uint32_t)lq[5] << 16);
    lv.w = (uint32_t)lq[6] | ((uint32_t)lq[7] << 16);
    *(uint4*)&g_colh[idx] = hv;
    *(uint4*)&g_coll[idx] = lv;
}

// ---------------- bf16x3 mma.sync GEMM + bias + ReLU -----------------------
// C[16384,256] = col[16384,2304] x wtB^T[2304,256], compensated bf16.
// CTA 128x128, 8 warps (2 m-rows x 4 n-cols), warp tile 64x32.
// K chunks of 16; single-stage SMEM with register prefetch overlap.
#define PADK 24   // bf16 elems per smem row (16 used, 48B stride: conflict-free)
__global__ __launch_bounds__(256) void gemm_bf(const float* __restrict__ bias,
                                               float* __restrict__ Cout) {
    __shared__ __align__(16) uint16_t sAh[128*PADK];
    __shared__ __align__(16) uint16_t sAl[128*PADK];
    __shared__ __align__(16) uint16_t sBh[128*PADK];
    __shared__ __align__(16) uint16_t sBl[128*PADK];

    int t = threadIdx.x;
    int wid = t >> 5, lane = t & 31;
    int n0 = blockIdx.x * 128;
    int m0 = blockIdx.y * 128;

    // staging role: row = t>>1 (0..127), half = t&1 (k 0-7 / 8-15)
    int srow = t >> 1, shalf = t & 1;
    const uint16_t* aH = g_colh + (size_t)(m0 + srow) * KD + shalf * 8;
    const uint16_t* aL = g_coll + (size_t)(m0 + srow) * KD + shalf * 8;
    const uint16_t* bH = g_wtBh + (size_t)(n0 + srow) * KD + shalf * 8;
    const uint16_t* bL = g_wtBl + (size_t)(n0 + srow) * KD + shalf * 8;
    int sidx = srow * PADK + shalf * 8;

    // ldmatrix lane addresses (constant across iterations)
    int sel = lane >> 3, r = lane & 7;
    uint32_t aOff = (uint32_t)((((wid & 1) * 64) + (sel & 1) * 8 + r) * (PADK*2) + (sel >> 1) * 16);
    uint32_t bOff = (uint32_t)((((wid >> 1) * 32) + (sel >> 1) * 8 + r) * (PADK*2) + (sel & 1) * 16);
    uint32_t aHad = smem_u32(sAh) + aOff;
    uint32_t aLad = smem_u32(sAl) + aOff;
    uint32_t bHad = smem_u32(sBh) + bOff;
    uint32_t bLad = smem_u32(sBl) + bOff;

    float acc[4][4][4];
    #pragma unroll
    for (int i = 0; i < 4; i++)
        #pragma unroll
        for (int j = 0; j < 4; j++)
            #pragma unroll
            for (int q = 0; q < 4; q++) acc[i][j][q] = 0.f;

    const int STEP16 = PADK * 16 * 2;   // byte stride for 16 rows

    for (int kt = 0; kt < KD/16; kt++) {
        int kc = kt * 16;
        uint4 rah = *(const uint4*)(aH + kc);
        uint4 ral = *(const uint4*)(aL + kc);
        uint4 rbh = *(const uint4*)(bH + kc);
        uint4 rbl = *(const uint4*)(bL + kc);

        __syncthreads();
        *(uint4*)&sAh[sidx] = rah;
        *(uint4*)&sAl[sidx] = ral;
        *(uint4*)&sBh[sidx] = rbh;
        *(uint4*)&sBl[sidx] = rbl;
        __syncthreads();

        uint32_t ah[4][4], al[4][4], bh[4][2], bl[4][2];
        #pragma unroll
        for (int i = 0; i < 4; i++) {
            LDSM4(ah[i][0], ah[i][1], ah[i][2], ah[i][3], aHad + i*STEP16);
            LDSM4(al[i][0], al[i][1], al[i][2], al[i][3], aLad + i*STEP16);
        }
        #pragma unroll
        for (int j = 0; j < 2; j++) {
            LDSM4(bh[2*j][0], bh[2*j][1], bh[2*j+1][0], bh[2*j+1][1], bHad + j*STEP16);
            LDSM4(bl[2*j][0], bl[2*j][1], bl[2*j+1][0], bl[2*j+1][1], bLad + j*STEP16);
        }

        #pragma unroll
        for (int i = 0; i < 4; i++)
            #pragma unroll
            for (int j = 0; j < 4; j++) {
                MMA_BF16(acc[i][j], ah[i], bh[j]);
                MMA_BF16(acc[i][j], ah[i], bl[j]);
                MMA_BF16(acc[i][j], al[i], bh[j]);
            }
    }

    // epilogue: c0,c1 at (row, 2col), c2,c3 at (row+8, 2col)
    int lr = lane >> 2, lc = (lane & 3) * 2;
    int mBase = m0 + (wid & 1) * 64 + lr;
    int nBase = n0 + (wid >> 1) * 32 + lc;
    #pragma unroll
    for (int j = 0; j < 4; j++) {
        int n = nBase + j * 8;
        float b0 = bias[n], b1 = bias[n + 1];
        #pragma unroll
        for (int i = 0; i < 4; i++) {
            int m = mBase + i * 16;
            float2 v0, v1;
            v0.x = fmaxf(acc[i][j][0] + b0, 0.f);
            v0.y = fmaxf(acc[i][j][1] + b1, 0.f);
            v1.x = fmaxf(acc[i][j][2] + b0, 0.f);
            v1.y = fmaxf(acc[i][j][3] + b1, 0.f);
            *(float2*)(Cout + (size_t)m*CHN + n)       = v0;
            *(float2*)(Cout + (size_t)(m+8)*CHN + n)   = v1;
        }
    }
}

// ---------------- launcher ---------------------------------------------------
extern "C" void kernel_launch(void* const* d_in, const int* in_sizes, int n_in,
                              void* d_out, int out_size) {
    const float* x = (const float*)d_in[0];
    const float* woff[3] = {(const float*)d_in[1], (const float*)d_in[5], (const float*)d_in[9]};
    const float* boff[3] = {(const float*)d_in[2], (const float*)d_in[6], (const float*)d_in[10]};
    const float* wm[3]   = {(const float*)d_in[3], (const float*)d_in[7], (const float*)d_in[11]};
    const float* bm[3]   = {(const float*)d_in[4], (const float*)d_in[8], (const float*)d_in[12]};
    float* out = (float*)d_out;

    float *act0, *act1;
    cudaGetSymbolAddress((void**)&act0, g_act0);
    cudaGetSymbolAddress((void**)&act1, g_act1);
    float* bufs[2] = {act0, act1};

    dim3 tb(32, 8);
    transpose2d<<<dim3(HW/32, CHN/32, BB), tb>>>(x, act0, CHN, HW);

    for (int L = 0; L < 3; L++) {
        const float* src = bufs[L & 1];
        float* dst = bufs[(L & 1) ^ 1];
        woff_trans_k<<<(KD*32 + 255)/256, 256>>>(woff[L]);
        wmain_trans_k<<<(CHN*KD + 255)/256, 256>>>(wm[L]);
        offset_conv_g<<<128, 256>>>(src, boff[L]);
        sample_k<<<(NP*9)/8, 256>>>(src);
        gemm_bf<<<dim3(2, 128), 256>>>(bm[L], dst);
    }

    transpose2d<<<dim3(CHN/32, HW/32, BB), tb>>>(bufs[1], out, HW, CHN);
}

// round 8
// speedup vs baseline: 2.1517x; 1.0493x over previous
#include <cuda_runtime.h>
#include <cuda_bf16.h>
#include <math.h>
#include <stdint.h>

#define BB 4
#define CHN 256
#define HH 64
#define WW 64
#define HW (HH*WW)        // 4096
#define NP (BB*HW)        // 16384 pixels
#define K9 9
#define KD (CHN*K9)       // 2304

// ---------------- scratch (device globals: allocation-free) ----------------
__device__ float g_act0[NP*CHN];                 // NHWC activations ping (16 MB)
__device__ float g_act1[NP*CHN];                 // pong
__device__ float g_om[NP*27];                    // offset-conv output [p][27]
__device__ uint16_t g_colh[(size_t)NP*KD];       // im2col bf16 hi (75.5 MB)
__device__ uint16_t g_coll[(size_t)NP*KD];       // im2col bf16 lo
__device__ uint16_t g_wtBh[CHN*KD];              // weight B[o][k] bf16 hi
__device__ uint16_t g_wtBl[CHN*KD];              // weight B[o][k] bf16 lo
__device__ uint16_t g_woffBh[32*KD];             // offset weight B[j][k] bf16 hi (27 used)
__device__ uint16_t g_woffBl[32*KD];             // offset weight B[j][k] bf16 lo

// ---------------- helpers ----------------------------------------------------
__device__ __forceinline__ uint32_t smem_u32(const void* p) {
    uint32_t a;
    asm("{ .reg .u64 t; cvta.to.shared.u64 t, %1; cvt.u32.u64 %0, t; }" : "=r"(a) : "l"(p));
    return a;
}
__device__ __forceinline__ uint16_t f2bf(float v) {
    __nv_bfloat16 b = __float2bfloat16(v);
    return *reinterpret_cast<uint16_t*>(&b);
}
__device__ __forceinline__ float bf2f(uint16_t u) {
    __nv_bfloat16 b = *reinterpret_cast<__nv_bfloat16*>(&u);
    return __bfloat162float(b);
}
__device__ __forceinline__ void bf_split(float v, uint16_t& h, uint16_t& l) {
    h = f2bf(v);
    float r = v - bf2f(h);
    l = f2bf(r);
}

#define LDSM4(r0, r1, r2, r3, addr) \
    asm volatile("ldmatrix.sync.aligned.m8n8.x4.shared.b16 {%0,%1,%2,%3}, [%4];" \
        : "=r"(r0), "=r"(r1), "=r"(r2), "=r"(r3) : "r"(addr))

#define MMA_BF16(d, a, b) \
    asm volatile("mma.sync.aligned.m16n8k16.row.col.f32.bf16.bf16.f32 " \
        "{%0,%1,%2,%3}, {%4,%5,%6,%7}, {%8,%9}, {%0,%1,%2,%3};" \
        : "+f"((d)[0]), "+f"((d)[1]), "+f"((d)[2]), "+f"((d)[3]) \
        : "r"((a)[0]), "r"((a)[1]), "r"((a)[2]), "r"((a)[3]), "r"((b)[0]), "r"((b)[1]))

// ---------------- generic 2D transpose (per-batch via grid.z) --------------
__global__ void transpose2d(const float* __restrict__ in, float* __restrict__ out,
                            int rows, int cols) {
    __shared__ float tile[32][33];
    int z = blockIdx.z;
    const float* ip = in + (size_t)z * rows * cols;
    float* op = out + (size_t)z * rows * cols;
    int c0 = blockIdx.x * 32, r0 = blockIdx.y * 32;
    int x = c0 + threadIdx.x;
    for (int i = threadIdx.y; i < 32; i += 8) {
        int r = r0 + i;
        tile[i][threadIdx.x] = (r < rows && x < cols) ? ip[(size_t)r*cols + x] : 0.f;
    }
    __syncthreads();
    int xo = r0 + threadIdx.x;
    for (int i = threadIdx.y; i < 32; i += 8) {
        int c = c0 + i;
        if (c < cols && xo < rows) op[(size_t)c*rows + xo] = tile[threadIdx.x][i];
    }
}

// ---------------- weight re-layouts ----------------------------------------
// g_woffBh/l[j*KD + kk*256 + c] = bf16 split of woff[(j*256+c)*9 + kk], j<27
__global__ void woff_trans_k(const float* __restrict__ woff) {
    int i = blockIdx.x * 256 + threadIdx.x;
    if (i >= 32*KD) return;
    int j = i / KD; int r = i - j*KD;
    int kk = r >> 8; int c = r & 255;
    float v = (j < 27) ? woff[(j*CHN + c)*9 + kk] : 0.f;
    uint16_t h, l;
    bf_split(v, h, l);
    g_woffBh[i] = h; g_woffBl[i] = l;
}

// g_wtBh/l[o*KD + kk*256 + c] = bf16 split of w[(o*256+c)*9 + kk]
__global__ void wmain_trans_k(const float* __restrict__ w) {
    int i = blockIdx.x * 256 + threadIdx.x;
    if (i >= CHN*KD) return;
    int o = i / KD; int r = i - o*KD;
    int kk = r >> 8; int c = r & 255;
    float v = w[((size_t)(o*CHN + c))*9 + kk];
    uint16_t h, l;
    bf_split(v, h, l);
    g_wtBh[i] = h; g_wtBl[i] = l;
}

// ---------------- offset conv: bf16x3 tensor-core implicit GEMM ------------
// M=16384 px, N=32 (27 used), K=2304. CTA = 128 px (2 rows x 64). 8 warps,
// warp tile 16x32. K chunks of 16 (each chunk lies within one tap kk).
#define PADK 24   // bf16 elems per smem row (48B stride: conflict-free ldmatrix)
__global__ __launch_bounds__(256) void offset_conv_mma(const float* __restrict__ xh,
                                                       const float* __restrict__ boff) {
    __shared__ __align__(16) uint16_t sAh[128*PADK];
    __shared__ __align__(16) uint16_t sAl[128*PADK];
    __shared__ __align__(16) uint16_t sBh[32*PADK];
    __shared__ __align__(16) uint16_t sBl[32*PADK];

    int bid = blockIdx.x;               // 128 blocks
    int b = bid >> 5, h0 = (bid & 31) * 2;
    int t = threadIdx.x;
    int wid = t >> 5, lane = t & 31;

    // A staging role: pixel srow (0..127), channel-half shalf (k 0-7 / 8-15)
    int srow = t >> 1, shalf = t & 1;
    int row_ld = srow >> 6, w_ld = srow & 63;
    int aSidx = srow * PADK + shalf * 8;
    // B staging role (t<64): j row, k-half
    int jrow = t >> 1;                  // used when t<64
    int bSidx = jrow * PADK + shalf * 8;

    // ldmatrix addresses
    int sel = lane >> 3, r8 = lane & 7;
    uint32_t aOff = (uint32_t)((wid*16 + (sel & 1)*8 + r8) * (PADK*2) + (sel >> 1) * 16);
    uint32_t bOff = (uint32_t)(((sel >> 1)*8 + r8) * (PADK*2) + (sel & 1) * 16);
    uint32_t aHad = smem_u32(sAh) + aOff;
    uint32_t aLad = smem_u32(sAl) + aOff;
    uint32_t bHad = smem_u32(sBh) + bOff;
    uint32_t bLad = smem_u32(sBl) + bOff;
    const int BSTEP16 = PADK * 16 * 2;

    float acc[4][4];
    #pragma unroll
    for (int j = 0; j < 4; j++)
        #pragma unroll
        for (int q = 0; q < 4; q++) acc[j][q] = 0.f;

    for (int kt = 0; kt < 144; kt++) {
        int kk = kt >> 4, c0 = (kt & 15) << 4;
        int rr = kk / 3, ss = kk - rr*3;
        // prefetch A (x patch with tap shift), convert to bf16 hi/lo
        int hy = h0 + row_ld + rr - 1;
        int wx = w_ld + ss - 1;
        bool v = ((unsigned)hy < (unsigned)HH) && ((unsigned)wx < (unsigned)WW);
        float4 q0 = make_float4(0,0,0,0), q1 = q0;
        if (v) {
            const float4* src = (const float4*)(xh + ((size_t)((b*HH + hy)*WW + wx))*CHN + c0 + shalf*8);
            q0 = src[0]; q1 = src[1];
        }
        uint16_t hq[8], lq[8];
        bf_split(q0.x, hq[0], lq[0]); bf_split(q0.y, hq[1], lq[1]);
        bf_split(q0.z, hq[2], lq[2]); bf_split(q0.w, hq[3], lq[3]);
        bf_split(q1.x, hq[4], lq[4]); bf_split(q1.y, hq[5], lq[5]);
        bf_split(q1.z, hq[6], lq[6]); bf_split(q1.w, hq[7], lq[7]);
        uint4 hv, lv;
        hv.x = (uint32_t)hq[0] | ((uint32_t)hq[1] << 16);
        hv.y = (uint32_t)hq[2] | ((uint32_t)hq[3] << 16);
        hv.z = (uint32_t)hq[4] | ((uint32_t)hq[5] << 16);
        hv.w = (uint32_t)hq[6] | ((uint32_t)hq[7] << 16);
        lv.x = (uint32_t)lq[0] | ((uint32_t)lq[1] << 16);
        lv.y = (uint32_t)lq[2] | ((uint32_t)lq[3] << 16);
        lv.z = (uint32_t)lq[4] | ((uint32_t)lq[5] << 16);
        lv.w = (uint32_t)lq[6] | ((uint32_t)lq[7] << 16);
        // prefetch B (already bf16 hi/lo)
        uint4 rbh, rbl;
        if (t < 64) {
            size_t bi = (size_t)jrow * KD + kt*16 + shalf*8;
            rbh = *(const uint4*)&g_woffBh[bi];
            rbl = *(const uint4*)&g_woffBl[bi];
        }

        __syncthreads();
        *(uint4*)&sAh[aSidx] = hv;
        *(uint4*)&sAl[aSidx] = lv;
        if (t < 64) {
            *(uint4*)&sBh[bSidx] = rbh;
            *(uint4*)&sBl[bSidx] = rbl;
        }
        __syncthreads();

        uint32_t ah[4], al[4], bh[4][2], bl[4][2];
        LDSM4(ah[0], ah[1], ah[2], ah[3], aHad);
        LDSM4(al[0], al[1], al[2], al[3], aLad);
        LDSM4(bh[0][0], bh[0][1], bh[1][0], bh[1][1], bHad);
        LDSM4(bh[2][0], bh[2][1], bh[3][0], bh[3][1], bHad + BSTEP16);
        LDSM4(bl[0][0], bl[0][1], bl[1][0], bl[1][1], bLad);
        LDSM4(bl[2][0], bl[2][1], bl[3][0], bl[3][1], bLad + BSTEP16);

        #pragma unroll
        for (int j = 0; j < 4; j++) {
            MMA_BF16(acc[j], ah, bh[j]);
            MMA_BF16(acc[j], ah, bl[j]);
            MMA_BF16(acc[j], al, bh[j]);
        }
    }

    // epilogue: write g_om[p][27] + bias (skip padded j >= 27)
    int lr = lane >> 2, lc = (lane & 3) * 2;
    int mBase = wid*16 + lr;
    #pragma unroll
    for (int j = 0; j < 4; j++) {
        int n = j*8 + lc;
        #pragma unroll
        for (int half = 0; half < 2; half++) {
            int m = mBase + half*8;
            int p = ((b*HH + h0 + (m >> 6))*WW + (m & 63));
            float* dst = g_om + (size_t)p*27;
            float v0 = acc[j][half*2 + 0];
            float v1 = acc[j][half*2 + 1];
            if (n < 27)     dst[n]     = v0 + boff[n];
            if (n + 1 < 27) dst[n + 1] = v1 + boff[n + 1];
        }
    }
}

// ---------------- bilinear sample + mask -> bf16 hi/lo im2col --------------
__global__ __launch_bounds__(256) void sample_k(const float* __restrict__ xh) {
    int wid = blockIdx.x * 8 + (threadIdx.x >> 5);
    int lane = threadIdx.x & 31;
    int p = wid / 9, k = wid - p*9;
    const float* omp = g_om + (size_t)p * 27;
    float dy = omp[2*k], dx = omp[2*k + 1];
    float mk = 1.f / (1.f + __expf(-omp[18 + k]));
    int b = p >> 12, hw = p & (HW - 1), h = hw >> 6, w = hw & 63;
    float ys = (float)(h + k/3 - 1) + dy;
    float xs = (float)(w + k%3 - 1) + dx;
    float y0f = floorf(ys), x0f = floorf(xs);
    float wy = ys - y0f, wx = xs - x0f;
    int y0 = (int)y0f, x0 = (int)x0f;
    int y1 = y0 + 1, x1 = x0 + 1;
    bool vy0 = ((unsigned)y0 < HH), vy1 = ((unsigned)y1 < HH);
    bool vx0 = ((unsigned)x0 < WW), vx1 = ((unsigned)x1 < WW);
    float w00 = (1.f - wy)*(1.f - wx)*mk;
    float w01 = (1.f - wy)*wx*mk;
    float w10 = wy*(1.f - wx)*mk;
    float w11 = wy*wx*mk;
    const float* base = xh + (size_t)b * HW * CHN;
    int c0 = lane * 8;
    const float4 z4 = make_float4(0.f, 0.f, 0.f, 0.f);
    float4 a00 = z4, b00 = z4, a01 = z4, b01 = z4;
    float4 a10 = z4, b10 = z4, a11 = z4, b11 = z4;
    if (vy0 && vx0) { const float4* q = (const float4*)(base + (size_t)(y0*WW + x0)*CHN + c0); a00 = q[0]; b00 = q[1]; }
    if (vy0 && vx1) { const float4* q = (const float4*)(base + (size_t)(y0*WW + x1)*CHN + c0); a01 = q[0]; b01 = q[1]; }
    if (vy1 && vx0) { const float4* q = (const float4*)(base + (size_t)(y1*WW + x0)*CHN + c0); a10 = q[0]; b10 = q[1]; }
    if (vy1 && vx1) { const float4* q = (const float4*)(base + (size_t)(y1*WW + x1)*CHN + c0); a11 = q[0]; b11 = q[1]; }
    float f[8];
    f[0] = w00*a00.x + w01*a01.x + w10*a10.x + w11*a11.x;
    f[1] = w00*a00.y + w01*a01.y + w10*a10.y + w11*a11.y;
    f[2] = w00*a00.z + w01*a01.z + w10*a10.z + w11*a11.z;
    f[3] = w00*a00.w + w01*a01.w + w10*a10.w + w11*a11.w;
    f[4] = w00*b00.x + w01*b01.x + w10*b10.x + w11*b11.x;
    f[5] = w00*b00.y + w01*b01.y + w10*b10.y + w11*b11.y;
    f[6] = w00*b00.z + w01*b01.z + w10*b10.z + w11*b11.z;
    f[7] = w00*b00.w + w01*b01.w + w10*b10.w + w11*b11.w;
    uint16_t hq[8], lq[8];
    #pragma unroll
    for (int q = 0; q < 8; q++) bf_split(f[q], hq[q], lq[q]);
    size_t idx = (size_t)wid*CHN + c0;
    uint4 hv, lv;
    hv.x = (uint32_t)hq[0] | ((uint32_t)hq[1] << 16);
    hv.y = (uint32_t)hq[2] | ((uint32_t)hq[3] << 16);
    hv.z = (uint32_t)hq[4] | ((uint32_t)hq[5] << 16);
    hv.w = (uint32_t)hq[6] | ((uint32_t)hq[7] << 16);
    lv.x = (uint32_t)lq[0] | ((uint32_t)lq[1] << 16);
    lv.y = (uint32_t)lq[2] | ((uint32_t)lq[3] << 16);
    lv.z = (uint32_t)lq[4] | ((uint32_t)lq[5] << 16);
    lv.w = (uint32_t)lq[6] | ((uint32_t)lq[7] << 16);
    *(uint4*)&g_colh[idx] = hv;
    *(uint4*)&g_coll[idx] = lv;
}

// ---------------- bf16x3 mma.sync GEMM + bias + ReLU -----------------------
__global__ __launch_bounds__(256) void gemm_bf(const float* __restrict__ bias,
                                               float* __restrict__ Cout) {
    __shared__ __align__(16) uint16_t sAh[128*PADK];
    __shared__ __align__(16) uint16_t sAl[128*PADK];
    __shared__ __align__(16) uint16_t sBh[128*PADK];
    __shared__ __align__(16) uint16_t sBl[128*PADK];

    int t = threadIdx.x;
    int wid = t >> 5, lane = t & 31;
    int n0 = blockIdx.x * 128;
    int m0 = blockIdx.y * 128;

    int srow = t >> 1, shalf = t & 1;
    const uint16_t* aH = g_colh + (size_t)(m0 + srow) * KD + shalf * 8;
    const uint16_t* aL = g_coll + (size_t)(m0 + srow) * KD + shalf * 8;
    const uint16_t* bH = g_wtBh + (size_t)(n0 + srow) * KD + shalf * 8;
    const uint16_t* bL = g_wtBl + (size_t)(n0 + srow) * KD + shalf * 8;
    int sidx = srow * PADK + shalf * 8;

    int sel = lane >> 3, r = lane & 7;
    uint32_t aOff = (uint32_t)((((wid & 1) * 64) + (sel & 1) * 8 + r) * (PADK*2) + (sel >> 1) * 16);
    uint32_t bOff = (uint32_t)((((wid >> 1) * 32) + (sel >> 1) * 8 + r) * (PADK*2) + (sel & 1) * 16);
    uint32_t aHad = smem_u32(sAh) + aOff;
    uint32_t aLad = smem_u32(sAl) + aOff;
    uint32_t bHad = smem_u32(sBh) + bOff;
    uint32_t bLad = smem_u32(sBl) + bOff;

    float acc[4][4][4];
    #pragma unroll
    for (int i = 0; i < 4; i++)
        #pragma unroll
        for (int j = 0; j < 4; j++)
            #pragma unroll
            for (int q = 0; q < 4; q++) acc[i][j][q] = 0.f;

    const int STEP16 = PADK * 16 * 2;

    for (int kt = 0; kt < KD/16; kt++) {
        int kc = kt * 16;
        uint4 rah = *(const uint4*)(aH + kc);
        uint4 ral = *(const uint4*)(aL + kc);
        uint4 rbh = *(const uint4*)(bH + kc);
        uint4 rbl = *(const uint4*)(bL + kc);

        __syncthreads();
        *(uint4*)&sAh[sidx] = rah;
        *(uint4*)&sAl[sidx] = ral;
        *(uint4*)&sBh[sidx] = rbh;
        *(uint4*)&sBl[sidx] = rbl;
        __syncthreads();

        uint32_t ah[4][4], al[4][4], bh[4][2], bl[4][2];
        #pragma unroll
        for (int i = 0; i < 4; i++) {
            LDSM4(ah[i][0], ah[i][1], ah[i][2], ah[i][3], aHad + i*STEP16);
            LDSM4(al[i][0], al[i][1], al[i][2], al[i][3], aLad + i*STEP16);
        }
        #pragma unroll
        for (int j = 0; j < 2; j++) {
            LDSM4(bh[2*j][0], bh[2*j][1], bh[2*j+1][0], bh[2*j+1][1], bHad + j*STEP16);
            LDSM4(bl[2*j][0], bl[2*j][1], bl[2*j+1][0], bl[2*j+1][1], bLad + j*STEP16);
        }

        #pragma unroll
        for (int i = 0; i < 4; i++)
            #pragma unroll
            for (int j = 0; j < 4; j++) {
                MMA_BF16(acc[i][j], ah[i], bh[j]);
                MMA_BF16(acc[i][j], ah[i], bl[j]);
                MMA_BF16(acc[i][j], al[i], bh[j]);
            }
    }

    int lr = lane >> 2, lc = (lane & 3) * 2;
    int mBase = m0 + (wid & 1) * 64 + lr;
    int nBase = n0 + (wid >> 1) * 32 + lc;
    #pragma unroll
    for (int j = 0; j < 4; j++) {
        int n = nBase + j * 8;
        float b0 = bias[n], b1 = bias[n + 1];
        #pragma unroll
        for (int i = 0; i < 4; i++) {
            int m = mBase + i * 16;
            float2 v0, v1;
            v0.x = fmaxf(acc[i][j][0] + b0, 0.f);
            v0.y = fmaxf(acc[i][j][1] + b1, 0.f);
            v1.x = fmaxf(acc[i][j][2] + b0, 0.f);
            v1.y = fmaxf(acc[i][j][3] + b1, 0.f);
            *(float2*)(Cout + (size_t)m*CHN + n)       = v0;
            *(float2*)(Cout + (size_t)(m+8)*CHN + n)   = v1;
        }
    }
}

// ---------------- launcher ---------------------------------------------------
extern "C" void kernel_launch(void* const* d_in, const int* in_sizes, int n_in,
                              void* d_out, int out_size) {
    const float* x = (const float*)d_in[0];
    const float* woff[3] = {(const float*)d_in[1], (const float*)d_in[5], (const float*)d_in[9]};
    const float* boff[3] = {(const float*)d_in[2], (const float*)d_in[6], (const float*)d_in[10]};
    const float* wm[3]   = {(const float*)d_in[3], (const float*)d_in[7], (const float*)d_in[11]};
    const float* bm[3]   = {(const float*)d_in[4], (const float*)d_in[8], (const float*)d_in[12]};
    float* out = (float*)d_out;

    float *act0, *act1;
    cudaGetSymbolAddress((void**)&act0, g_act0);
    cudaGetSymbolAddress((void**)&act1, g_act1);
    float* bufs[2] = {act0, act1};

    dim3 tb(32, 8);
    transpose2d<<<dim3(HW/32, CHN/32, BB), tb>>>(x, act0, CHN, HW);

    for (int L = 0; L < 3; L++) {
        const float* src = bufs[L & 1];
        float* dst = bufs[(L & 1) ^ 1];
        woff_trans_k<<<(32*KD + 255)/256, 256>>>(woff[L]);
        wmain_trans_k<<<(CHN*KD + 255)/256, 256>>>(wm[L]);
        offset_conv_mma<<<128, 256>>>(src, boff[L]);
        sample_k<<<(NP*9)/8, 256>>>(src);
        gemm_bf<<<dim3(2, 128), 256>>>(bm[L], dst);
    }

    transpose2d<<<dim3(CHN/32, HW/32, BB), tb>>>(bufs[1], out, HW, CHN);
}

// round 10
// speedup vs baseline: 2.4358x; 1.1320x over previous
#include <cuda_runtime.h>
#include <cuda_bf16.h>
#include <math.h>
#include <stdint.h>

#define BB 4
#define CHN 256
#define HH 64
#define WW 64
#define HW (HH*WW)        // 4096
#define NP (BB*HW)        // 16384 pixels
#define K9 9
#define KD (CHN*K9)       // 2304

// ---------------- scratch (device globals: allocation-free) ----------------
__device__ float g_act0[NP*CHN];                 // NHWC activations ping (16 MB)
__device__ float g_act1[NP*CHN];                 // pong
__device__ float g_om[NP*27];                    // offset-conv output [p][27]
__device__ float g_omp[(size_t)3*NP*32];         // offset-conv partials [g][p][32]
__device__ uint16_t g_colh[(size_t)NP*KD];       // im2col bf16 hi (75.5 MB)
__device__ uint16_t g_coll[(size_t)NP*KD];       // im2col bf16 lo
__device__ uint16_t g_wtBh[CHN*KD];              // weight B[o][k] bf16 hi
__device__ uint16_t g_wtBl[CHN*KD];              // weight B[o][k] bf16 lo
__device__ uint16_t g_woffBh[32*KD];             // offset weight B[j][k] bf16 hi (27 used)
__device__ uint16_t g_woffBl[32*KD];             // offset weight B[j][k] bf16 lo

// ---------------- helpers ----------------------------------------------------
__device__ __forceinline__ uint32_t smem_u32(const void* p) {
    uint32_t a;
    asm("{ .reg .u64 t; cvta.to.shared.u64 t, %1; cvt.u32.u64 %0, t; }" : "=r"(a) : "l"(p));
    return a;
}
__device__ __forceinline__ uint16_t f2bf(float v) {
    __nv_bfloat16 b = __float2bfloat16(v);
    return *reinterpret_cast<uint16_t*>(&b);
}
__device__ __forceinline__ float bf2f(uint16_t u) {
    __nv_bfloat16 b = *reinterpret_cast<__nv_bfloat16*>(&u);
    return __bfloat162float(b);
}
__device__ __forceinline__ void bf_split(float v, uint16_t& h, uint16_t& l) {
    h = f2bf(v);
    float r = v - bf2f(h);
    l = f2bf(r);
}

#define LDSM4(r0, r1, r2, r3, addr) \
    asm volatile("ldmatrix.sync.aligned.m8n8.x4.shared.b16 {%0,%1,%2,%3}, [%4];" \
        : "=r"(r0), "=r"(r1), "=r"(r2), "=r"(r3) : "r"(addr))

#define MMA_BF16(d, a, b) \
    asm volatile("mma.sync.aligned.m16n8k16.row.col.f32.bf16.bf16.f32 " \
        "{%0,%1,%2,%3}, {%4,%5,%6,%7}, {%8,%9}, {%0,%1,%2,%3};" \
        : "+f"((d)[0]), "+f"((d)[1]), "+f"((d)[2]), "+f"((d)[3]) \
        : "r"((a)[0]), "r"((a)[1]), "r"((a)[2]), "r"((a)[3]), "r"((b)[0]), "r"((b)[1]))

// ---------------- generic 2D transpose (per-batch via grid.z) --------------
__global__ void transpose2d(const float* __restrict__ in, float* __restrict__ out,
                            int rows, int cols) {
    __shared__ float tile[32][33];
    int z = blockIdx.z;
    const float* ip = in + (size_t)z * rows * cols;
    float* op = out + (size_t)z * rows * cols;
    int c0 = blockIdx.x * 32, r0 = blockIdx.y * 32;
    int x = c0 + threadIdx.x;
    for (int i = threadIdx.y; i < 32; i += 8) {
        int r = r0 + i;
        tile[i][threadIdx.x] = (r < rows && x < cols) ? ip[(size_t)r*cols + x] : 0.f;
    }
    __syncthreads();
    int xo = r0 + threadIdx.x;
    for (int i = threadIdx.y; i < 32; i += 8) {
        int c = c0 + i;
        if (c < cols && xo < rows) op[(size_t)c*rows + xo] = tile[threadIdx.x][i];
    }
}

// ---------------- weight re-layouts ----------------------------------------
// g_woffBh/l[j*KD + kk*256 + c] = bf16 split of woff[(j*256+c)*9 + kk], j<27
__global__ void woff_trans_k(const float* __restrict__ woff) {
    int i = blockIdx.x * 256 + threadIdx.x;
    if (i >= 32*KD) return;
    int j = i / KD; int r = i - j*KD;
    int kk = r >> 8; int c = r & 255;
    float v = (j < 27) ? woff[(j*CHN + c)*9 + kk] : 0.f;
    uint16_t h, l;
    bf_split(v, h, l);
    g_woffBh[i] = h; g_woffBl[i] = l;
}

// g_wtBh/l[o*KD + kk*256 + c] = bf16 split of w[(o*256+c)*9 + kk]
__global__ void wmain_trans_k(const float* __restrict__ w) {
    int i = blockIdx.x * 256 + threadIdx.x;
    if (i >= CHN*KD) return;
    int o = i / KD; int r = i - o*KD;
    int kk = r >> 8; int c = r & 255;
    float v = w[((size_t)(o*CHN + c))*9 + kk];
    uint16_t h, l;
    bf_split(v, h, l);
    g_wtBh[i] = h; g_wtBl[i] = l;
}

// ---------------- offset conv: bf16x3 tensor-core implicit GEMM ------------
// K-split across 3 CTA groups (3 taps each). CTA = 128 px x 32 j, 48 k-iters.
#define PADK 24   // bf16 elems per smem row (48B stride: conflict-free ldmatrix)
__global__ __launch_bounds__(256) void offset_conv_mma(const float* __restrict__ xh) {
    __shared__ __align__(16) uint16_t sAh[128*PADK];
    __shared__ __align__(16) uint16_t sAl[128*PADK];
    __shared__ __align__(16) uint16_t sBh[32*PADK];
    __shared__ __align__(16) uint16_t sBl[32*PADK];

    int bid = blockIdx.x;               // 128 blocks
    int g = blockIdx.y;                 // tap group: taps 3g..3g+2
    int b = bid >> 5, h0 = (bid & 31) * 2;
    int t = threadIdx.x;
    int wid = t >> 5, lane = t & 31;

    int srow = t >> 1, shalf = t & 1;
    int row_ld = srow >> 6, w_ld = srow & 63;
    int aSidx = srow * PADK + shalf * 8;
    int jrow = t >> 1;                  // used when t<64
    int bSidx = jrow * PADK + shalf * 8;

    int sel = lane >> 3, r8 = lane & 7;
    uint32_t aOff = (uint32_t)((wid*16 + (sel & 1)*8 + r8) * (PADK*2) + (sel >> 1) * 16);
    uint32_t bOff = (uint32_t)(((sel >> 1)*8 + r8) * (PADK*2) + (sel & 1) * 16);
    uint32_t aHad = smem_u32(sAh) + aOff;
    uint32_t aLad = smem_u32(sAl) + aOff;
    uint32_t bHad = smem_u32(sBh) + bOff;
    uint32_t bLad = smem_u32(sBl) + bOff;
    const int BSTEP16 = PADK * 16 * 2;

    float acc[4][4];
    #pragma unroll
    for (int j = 0; j < 4; j++)
        #pragma unroll
        for (int q = 0; q < 4; q++) acc[j][q] = 0.f;

    for (int kt = 0; kt < 48; kt++) {
        int kk = g*3 + (kt >> 4), c0 = (kt & 15) << 4;
        int rr = kk / 3, ss = kk - rr*3;
        int hy = h0 + row_ld + rr - 1;
        int wx = w_ld + ss - 1;
        bool v = ((unsigned)hy < (unsigned)HH) && ((unsigned)wx < (unsigned)WW);
        float4 q0 = make_float4(0,0,0,0), q1 = q0;
        if (v) {
            const float4* src = (const float4*)(xh + ((size_t)((b*HH + hy)*WW + wx))*CHN + c0 + shalf*8);
            q0 = src[0]; q1 = src[1];
        }
        uint16_t hq[8], lq[8];
        bf_split(q0.x, hq[0], lq[0]); bf_split(q0.y, hq[1], lq[1]);
        bf_split(q0.z, hq[2], lq[2]); bf_split(q0.w, hq[3], lq[3]);
        bf_split(q1.x, hq[4], lq[4]); bf_split(q1.y, hq[5], lq[5]);
        bf_split(q1.z, hq[6], lq[6]); bf_split(q1.w, hq[7], lq[7]);
        uint4 hv, lv;
        hv.x = (uint32_t)hq[0] | ((uint32_t)hq[1] << 16);
        hv.y = (uint32_t)hq[2] | ((uint32_t)hq[3] << 16);
        hv.z = (uint32_t)hq[4] | ((uint32_t)hq[5] << 16);
        hv.w = (uint32_t)hq[6] | ((uint32_t)hq[7] << 16);
        lv.x = (uint32_t)lq[0] | ((uint32_t)lq[1] << 16);
        lv.y = (uint32_t)lq[2] | ((uint32_t)lq[3] << 16);
        lv.z = (uint32_t)lq[4] | ((uint32_t)lq[5] << 16);
        lv.w = (uint32_t)lq[6] | ((uint32_t)lq[7] << 16);
        uint4 rbh, rbl;
        if (t < 64) {
            size_t bi = (size_t)jrow * KD + ((size_t)kk << 8) + c0 + shalf*8;
            rbh = *(const uint4*)&g_woffBh[bi];
            rbl = *(const uint4*)&g_woffBl[bi];
        }

        __syncthreads();
        *(uint4*)&sAh[aSidx] = hv;
        *(uint4*)&sAl[aSidx] = lv;
        if (t < 64) {
            *(uint4*)&sBh[bSidx] = rbh;
            *(uint4*)&sBl[bSidx] = rbl;
        }
        __syncthreads();

        uint32_t ah[4], al[4], bh[4][2], bl[4][2];
        LDSM4(ah[0], ah[1], ah[2], ah[3], aHad);
        LDSM4(al[0], al[1], al[2], al[3], aLad);
        LDSM4(bh[0][0], bh[0][1], bh[1][0], bh[1][1], bHad);
        LDSM4(bh[2][0], bh[2][1], bh[3][0], bh[3][1], bHad + BSTEP16);
        LDSM4(bl[0][0], bl[0][1], bl[1][0], bl[1][1], bLad);
        LDSM4(bl[2][0], bl[2][1], bl[3][0], bl[3][1], bLad + BSTEP16);

        #pragma unroll
        for (int j = 0; j < 4; j++) {
            MMA_BF16(acc[j], ah, bh[j]);
            MMA_BF16(acc[j], ah, bl[j]);
            MMA_BF16(acc[j], al, bh[j]);
        }
    }

    // epilogue: partials to g_omp[g][p][32] (padded, no guards)
    int lr = lane >> 2, lc = (lane & 3) * 2;
    int mBase = wid*16 + lr;
    float* gout = g_omp + (size_t)g * NP * 32;
    #pragma unroll
    for (int j = 0; j < 4; j++) {
        int n = j*8 + lc;
        #pragma unroll
        for (int half = 0; half < 2; half++) {
            int m = mBase + half*8;
            int p = ((b*HH + h0 + (m >> 6))*WW + (m & 63));
            *(float2*)(gout + (size_t)p*32 + n) =
                make_float2(acc[j][half*2 + 0], acc[j][half*2 + 1]);
        }
    }
}

// ---------------- reduce partials + bias -> g_om ---------------------------
__global__ __launch_bounds__(256) void om_reduce_k(const float* __restrict__ boff) {
    int idx = blockIdx.x * 256 + threadIdx.x;
    if (idx >= NP*27) return;
    int p = idx / 27, j = idx - p*27;
    float v = g_omp[(size_t)p*32 + j]
            + g_omp[(size_t)(NP + p)*32 + j]
            + g_omp[(size_t)(2*NP + p)*32 + j]
            + boff[j];
    g_om[idx] = v;
}

// ---------------- bilinear sample + mask -> bf16 hi/lo im2col --------------
__global__ __launch_bounds__(256) void sample_k(const float* __restrict__ xh) {
    int wid = blockIdx.x * 8 + (threadIdx.x >> 5);
    int lane = threadIdx.x & 31;
    int p = wid / 9, k = wid - p*9;
    const float* omp = g_om + (size_t)p * 27;
    float dy = omp[2*k], dx = omp[2*k + 1];
    float mk = 1.f / (1.f + __expf(-omp[18 + k]));
    int b = p >> 12, hw = p & (HW - 1), h = hw >> 6, w = hw & 63;
    float ys = (float)(h + k/3 - 1) + dy;
    float xs = (float)(w + k%3 - 1) + dx;
    float y0f = floorf(ys), x0f = floorf(xs);
    float wy = ys - y0f, wx = xs - x0f;
    int y0 = (int)y0f, x0 = (int)x0f;
    int y1 = y0 + 1, x1 = x0 + 1;
    bool vy0 = ((unsigned)y0 < HH), vy1 = ((unsigned)y1 < HH);
    bool vx0 = ((unsigned)x0 < WW), vx1 = ((unsigned)x1 < WW);
    float w00 = (1.f - wy)*(1.f - wx)*mk;
    float w01 = (1.f - wy)*wx*mk;
    float w10 = wy*(1.f - wx)*mk;
    float w11 = wy*wx*mk;
    const float* base = xh + (size_t)b * HW * CHN;
    int c0 = lane * 8;
    const float4 z4 = make_float4(0.f, 0.f, 0.f, 0.f);
    float4 a00 = z4, b00 = z4, a01 = z4, b01 = z4;
    float4 a10 = z4, b10 = z4, a11 = z4, b11 = z4;
    if (vy0 && vx0) { const float4* q = (const float4*)(base + (size_t)(y0*WW + x0)*CHN + c0); a00 = q[0]; b00 = q[1]; }
    if (vy0 && vx1) { const float4* q = (const float4*)(base + (size_t)(y0*WW + x1)*CHN + c0); a01 = q[0]; b01 = q[1]; }
    if (vy1 && vx0) { const float4* q = (const float4*)(base + (size_t)(y1*WW + x0)*CHN + c0); a10 = q[0]; b10 = q[1]; }
    if (vy1 && vx1) { const float4* q = (const float4*)(base + (size_t)(y1*WW + x1)*CHN + c0); a11 = q[0]; b11 = q[1]; }
    float f[8];
    f[0] = w00*a00.x + w01*a01.x + w10*a10.x + w11*a11.x;
    f[1] = w00*a00.y + w01*a01.y + w10*a10.y + w11*a11.y;
    f[2] = w00*a00.z + w01*a01.z + w10*a10.z + w11*a11.z;
    f[3] = w00*a00.w + w01*a01.w + w10*a10.w + w11*a11.w;
    f[4] = w00*b00.x + w01*b01.x + w10*b10.x + w11*b11.x;
    f[5] = w00*b00.y + w01*b01.y + w10*b10.y + w11*b11.y;
    f[6] = w00*b00.z + w01*b01.z + w10*b10.z + w11*b11.z;
    f[7] = w00*b00.w + w01*b01.w + w10*b10.w + w11*b11.w;
    uint16_t hq[8], lq[8];
    #pragma unroll
    for (int q = 0; q < 8; q++) bf_split(f[q], hq[q], lq[q]);
    size_t idx = (size_t)wid*CHN + c0;
    uint4 hv, lv;
    hv.x = (uint32_t)hq[0] | ((uint32_t)hq[1] << 16);
    hv.y = (uint32_t)hq[2] | ((uint32_t)hq[3] << 16);
    hv.z = (uint32_t)hq[4] | ((uint32_t)hq[5] << 16);
    hv.w = (uint32_t)hq[6] | ((uint32_t)hq[7] << 16);
    lv.x = (uint32_t)lq[0] | ((uint32_t)lq[1] << 16);
    lv.y = (uint32_t)lq[2] | ((uint32_t)lq[3] << 16);
    lv.z = (uint32_t)lq[4] | ((uint32_t)lq[5] << 16);
    lv.w = (uint32_t)lq[6] | ((uint32_t)lq[7] << 16);
    *(uint4*)&g_colh[idx] = hv;
    *(uint4*)&g_coll[idx] = lv;
}

// ---------------- bf16x3 mma.sync GEMM + bias + ReLU -----------------------
__global__ __launch_bounds__(256) void gemm_bf(const float* __restrict__ bias,
                                               float* __restrict__ Cout) {
    __shared__ __align__(16) uint16_t sAh[128*PADK];
    __shared__ __align__(16) uint16_t sAl[128*PADK];
    __shared__ __align__(16) uint16_t sBh[128*PADK];
    __shared__ __align__(16) uint16_t sBl[128*PADK];

    int t = threadIdx.x;
    int wid = t >> 5, lane = t & 31;
    int n0 = blockIdx.x * 128;
    int m0 = blockIdx.y * 128;

    int srow = t >> 1, shalf = t & 1;
    const uint16_t* aH = g_colh + (size_t)(m0 + srow) * KD + shalf * 8;
    const uint16_t* aL = g_coll + (size_t)(m0 + srow) * KD + shalf * 8;
    const uint16_t* bH = g_wtBh + (size_t)(n0 + srow) * KD + shalf * 8;
    const uint16_t* bL = g_wtBl + (size_t)(n0 + srow) * KD + shalf * 8;
    int sidx = srow * PADK + shalf * 8;

    int sel = lane >> 3, r = lane & 7;
    uint32_t aOff = (uint32_t)((((wid & 1) * 64) + (sel & 1) * 8 + r) * (PADK*2) + (sel >> 1) * 16);
    uint32_t bOff = (uint32_t)((((wid >> 1) * 32) + (sel >> 1) * 8 + r) * (PADK*2) + (sel & 1) * 16);
    uint32_t aHad = smem_u32(sAh) + aOff;
    uint32_t aLad = smem_u32(sAl) + aOff;
    uint32_t bHad = smem_u32(sBh) + bOff;
    uint32_t bLad = smem_u32(sBl) + bOff;

    float acc[4][4][4];
    #pragma unroll
    for (int i = 0; i < 4; i++)
        #pragma unroll
        for (int j = 0; j < 4; j++)
            #pragma unroll
            for (int q = 0; q < 4; q++) acc[i][j][q] = 0.f;

    const int STEP16 = PADK * 16 * 2;

    for (int kt = 0; kt < KD/16; kt++) {
        int kc = kt * 16;
        uint4 rah = *(const uint4*)(aH + kc);
        uint4 ral = *(const uint4*)(aL + kc);
        uint4 rbh = *(const uint4*)(bH + kc);
        uint4 rbl = *(const uint4*)(bL + kc);

        __syncthreads();
        *(uint4*)&sAh[sidx] = rah;
        *(uint4*)&sAl[sidx] = ral;
        *(uint4*)&sBh[sidx] = rbh;
        *(uint4*)&sBl[sidx] = rbl;
        __syncthreads();

        uint32_t ah[4][4], al[4][4], bh[4][2], bl[4][2];
        #pragma unroll
        for (int i = 0; i < 4; i++) {
            LDSM4(ah[i][0], ah[i][1], ah[i][2], ah[i][3], aHad + i*STEP16);
            LDSM4(al[i][0], al[i][1], al[i][2], al[i][3], aLad + i*STEP16);
        }
        #pragma unroll
        for (int j = 0; j < 2; j++) {
            LDSM4(bh[2*j][0], bh[2*j][1], bh[2*j+1][0], bh[2*j+1][1], bHad + j*STEP16);
            LDSM4(bl[2*j][0], bl[2*j][1], bl[2*j+1][0], bl[2*j+1][1], bLad + j*STEP16);
        }

        #pragma unroll
        for (int i = 0; i < 4; i++)
            #pragma unroll
            for (int j = 0; j < 4; j++) {
                MMA_BF16(acc[i][j], ah[i], bh[j]);
                MMA_BF16(acc[i][j], ah[i], bl[j]);
                MMA_BF16(acc[i][j], al[i], bh[j]);
            }
    }

    int lr = lane >> 2, lc = (lane & 3) * 2;
    int mBase = m0 + (wid & 1) * 64 + lr;
    int nBase = n0 + (wid >> 1) * 32 + lc;
    #pragma unroll
    for (int j = 0; j < 4; j++) {
        int n = nBase + j * 8;
        float b0 = bias[n], b1 = bias[n + 1];
        #pragma unroll
        for (int i = 0; i < 4; i++) {
            int m = mBase + i * 16;
            float2 v0, v1;
            v0.x = fmaxf(acc[i][j][0] + b0, 0.f);
            v0.y = fmaxf(acc[i][j][1] + b1, 0.f);
            v1.x = fmaxf(acc[i][j][2] + b0, 0.f);
            v1.y = fmaxf(acc[i][j][3] + b1, 0.f);
            *(float2*)(Cout + (size_t)m*CHN + n)       = v0;
            *(float2*)(Cout + (size_t)(m+8)*CHN + n)   = v1;
        }
    }
}

// ---------------- launcher ---------------------------------------------------
extern "C" void kernel_launch(void* const* d_in, const int* in_sizes, int n_in,
                              void* d_out, int out_size) {
    const float* x = (const float*)d_in[0];
    const float* woff[3] = {(const float*)d_in[1], (const float*)d_in[5], (const float*)d_in[9]};
    const float* boff[3] = {(const float*)d_in[2], (const float*)d_in[6], (const float*)d_in[10]};
    const float* wm[3]   = {(const float*)d_in[3], (const float*)d_in[7], (const float*)d_in[11]};
    const float* bm[3]   = {(const float*)d_in[4], (const float*)d_in[8], (const float*)d_in[12]};
    float* out = (float*)d_out;

    float *act0, *act1;
    cudaGetSymbolAddress((void**)&act0, g_act0);
    cudaGetSymbolAddress((void**)&act1, g_act1);
    float* bufs[2] = {act0, act1};

    dim3 tb(32, 8);
    transpose2d<<<dim3(HW/32, CHN/32, BB), tb>>>(x, act0, CHN, HW);

    for (int L = 0; L < 3; L++) {
        const float* src = bufs[L & 1];
        float* dst = bufs[(L & 1) ^ 1];
        woff_trans_k<<<(32*KD + 255)/256, 256>>>(woff[L]);
        wmain_trans_k<<<(CHN*KD + 255)/256, 256>>>(wm[L]);
        offset_conv_mma<<<dim3(128, 3), 256>>>(src);
        om_reduce_k<<<(NP*27 + 255)/256, 256>>>(boff[L]);
        sample_k<<<(NP*9)/8, 256>>>(src);
        gemm_bf<<<dim3(2, 128), 256>>>(bm[L], dst);
    }

    transpose2d<<<dim3(CHN/32, HW/32, BB), tb>>>(bufs[1], out, HW, CHN);
}

// round 13
// speedup vs baseline: 2.7276x; 1.1198x over previous
#include <cuda_runtime.h>
#include <cuda_bf16.h>
#include <math.h>
#include <stdint.h>

#define BB 4
#define CHN 256
#define HH 64
#define WW 64
#define HW (HH*WW)        // 4096
#define NP (BB*HW)        // 16384 pixels
#define K9 9
#define KD (CHN*K9)       // 2304

// ---------------- scratch (device globals: allocation-free) ----------------
__device__ float g_act0[NP*CHN];                 // NHWC activations ping (16 MB)
__device__ float g_act1[NP*CHN];                 // pong
__device__ float g_om[NP*27];                    // offset-conv output [p][27]
__device__ float g_omp[(size_t)3*NP*32];         // offset-conv partials [g][p][32]
__device__ uint16_t g_colh[(size_t)NP*KD];       // im2col bf16 hi (75.5 MB)
__device__ uint16_t g_coll[(size_t)NP*KD];       // im2col bf16 lo
__device__ uint16_t g_wtBh[CHN*KD];              // weight B[o][k] bf16 hi
__device__ uint16_t g_wtBl[CHN*KD];              // weight B[o][k] bf16 lo
__device__ uint16_t g_woffBh[32*KD];             // offset weight B[j][k] bf16 hi (27 used)
__device__ uint16_t g_woffBl[32*KD];             // offset weight B[j][k] bf16 lo

// ---------------- helpers ----------------------------------------------------
__device__ __forceinline__ uint32_t smem_u32(const void* p) {
    uint32_t a;
    asm("{ .reg .u64 t; cvta.to.shared.u64 t, %1; cvt.u32.u64 %0, t; }" : "=r"(a) : "l"(p));
    return a;
}
__device__ __forceinline__ uint16_t f2bf(float v) {
    __nv_bfloat16 b = __float2bfloat16(v);
    return *reinterpret_cast<uint16_t*>(&b);
}
__device__ __forceinline__ float bf2f(uint16_t u) {
    __nv_bfloat16 b = *reinterpret_cast<__nv_bfloat16*>(&u);
    return __bfloat162float(b);
}
__device__ __forceinline__ void bf_split(float v, uint16_t& h, uint16_t& l) {
    h = f2bf(v);
    float r = v - bf2f(h);
    l = f2bf(r);
}
__device__ __forceinline__ void cp16(uint32_t dst, const void* src) {
    asm volatile("cp.async.cg.shared.global [%0], [%1], 16;" :: "r"(dst), "l"(src));
}
#define CP_COMMIT() asm volatile("cp.async.commit_group;" ::: "memory")
#define CP_WAIT2()  asm volatile("cp.async.wait_group 2;" ::: "memory")

#define LDSM4(r0, r1, r2, r3, addr) \
    asm volatile("ldmatrix.sync.aligned.m8n8.x4.shared.b16 {%0,%1,%2,%3}, [%4];" \
        : "=r"(r0), "=r"(r1), "=r"(r2), "=r"(r3) : "r"(addr))

#define MMA_BF16(d, a, b) \
    asm volatile("mma.sync.aligned.m16n8k16.row.col.f32.bf16.bf16.f32 " \
        "{%0,%1,%2,%3}, {%4,%5,%6,%7}, {%8,%9}, {%0,%1,%2,%3};" \
        : "+f"((d)[0]), "+f"((d)[1]), "+f"((d)[2]), "+f"((d)[3]) \
        : "r"((a)[0]), "r"((a)[1]), "r"((a)[2]), "r"((a)[3]), "r"((b)[0]), "r"((b)[1]))

// ---------------- generic 2D transpose (per-batch via grid.z) --------------
__global__ void transpose2d(const float* __restrict__ in, float* __restrict__ out,
                            int rows, int cols) {
    __shared__ float tile[32][33];
    int z = blockIdx.z;
    const float* ip = in + (size_t)z * rows * cols;
    float* op = out + (size_t)z * rows * cols;
    int c0 = blockIdx.x * 32, r0 = blockIdx.y * 32;
    int x = c0 + threadIdx.x;
    for (int i = threadIdx.y; i < 32; i += 8) {
        int r = r0 + i;
        tile[i][threadIdx.x] = (r < rows && x < cols) ? ip[(size_t)r*cols + x] : 0.f;
    }
    __syncthreads();
    int xo = r0 + threadIdx.x;
    for (int i = threadIdx.y; i < 32; i += 8) {
        int c = c0 + i;
        if (c < cols && xo < rows) op[(size_t)c*rows + xo] = tile[threadIdx.x][i];
    }
}

// ---------------- weight re-layouts ----------------------------------------
// g_woffBh/l[j*KD + kk*256 + c] = bf16 split of woff[(j*256+c)*9 + kk], j<27
__global__ void woff_trans_k(const float* __restrict__ woff) {
    int i = blockIdx.x * 256 + threadIdx.x;
    if (i >= 32*KD) return;
    int j = i / KD; int r = i - j*KD;
    int kk = r >> 8; int c = r & 255;
    float v = (j < 27) ? woff[(j*CHN + c)*9 + kk] : 0.f;
    uint16_t h, l;
    bf_split(v, h, l);
    g_woffBh[i] = h; g_woffBl[i] = l;
}

// g_wtBh/l[o*KD + kk*256 + c] = bf16 split of w[(o*256+c)*9 + kk]
__global__ void wmain_trans_k(const float* __restrict__ w) {
    int i = blockIdx.x * 256 + threadIdx.x;
    if (i >= CHN*KD) return;
    int o = i / KD; int r = i - o*KD;
    int kk = r >> 8; int c = r & 255;
    float v = w[((size_t)(o*CHN + c))*9 + kk];
    uint16_t h, l;
    bf_split(v, h, l);
    g_wtBh[i] = h; g_wtBl[i] = l;
}

// ---------------- offset conv: bf16x3 tensor-core implicit GEMM ------------
// K-split across 3 CTA groups (3 taps each). CTA = 128 px x 32 j, 48 k-iters.
#define PADK 24   // bf16 elems per smem row (48B stride: conflict-free ldmatrix)
__global__ __launch_bounds__(256) void offset_conv_mma(const float* __restrict__ xh) {
    __shared__ __align__(16) uint16_t sAh[128*PADK];
    __shared__ __align__(16) uint16_t sAl[128*PADK];
    __shared__ __align__(16) uint16_t sBh[32*PADK];
    __shared__ __align__(16) uint16_t sBl[32*PADK];

    int bid = blockIdx.x;               // 128 blocks
    int g = blockIdx.y;                 // tap group: taps 3g..3g+2
    int b = bid >> 5, h0 = (bid & 31) * 2;
    int t = threadIdx.x;
    int wid = t >> 5, lane = t & 31;

    int srow = t >> 1, shalf = t & 1;
    int row_ld = srow >> 6, w_ld = srow & 63;
    int aSidx = srow * PADK + shalf * 8;
    int jrow = t >> 1;                  // used when t<64
    int bSidx = jrow * PADK + shalf * 8;

    int sel = lane >> 3, r8 = lane & 7;
    uint32_t aOff = (uint32_t)((wid*16 + (sel & 1)*8 + r8) * (PADK*2) + (sel >> 1) * 16);
    uint32_t bOff = (uint32_t)(((sel >> 1)*8 + r8) * (PADK*2) + (sel & 1) * 16);
    uint32_t aHad = smem_u32(sAh) + aOff;
    uint32_t aLad = smem_u32(sAl) + aOff;
    uint32_t bHad = smem_u32(sBh) + bOff;
    uint32_t bLad = smem_u32(sBl) + bOff;
    const int BSTEP16 = PADK * 16 * 2;

    float acc[4][4];
    #pragma unroll
    for (int j = 0; j < 4; j++)
        #pragma unroll
        for (int q = 0; q < 4; q++) acc[j][q] = 0.f;

    for (int kt = 0; kt < 48; kt++) {
        int kk = g*3 + (kt >> 4), c0 = (kt & 15) << 4;
        int rr = kk / 3, ss = kk - rr*3;
        int hy = h0 + row_ld + rr - 1;
        int wx = w_ld + ss - 1;
        bool v = ((unsigned)hy < (unsigned)HH) && ((unsigned)wx < (unsigned)WW);
        float4 q0 = make_float4(0,0,0,0), q1 = q0;
        if (v) {
            const float4* src = (const float4*)(xh + ((size_t)((b*HH + hy)*WW + wx))*CHN + c0 + shalf*8);
            q0 = src[0]; q1 = src[1];
        }
        uint16_t hq[8], lq[8];
        bf_split(q0.x, hq[0], lq[0]); bf_split(q0.y, hq[1], lq[1]);
        bf_split(q0.z, hq[2], lq[2]); bf_split(q0.w, hq[3], lq[3]);
        bf_split(q1.x, hq[4], lq[4]); bf_split(q1.y, hq[5], lq[5]);
        bf_split(q1.z, hq[6], lq[6]); bf_split(q1.w, hq[7], lq[7]);
        uint4 hv, lv;
        hv.x = (uint32_t)hq[0] | ((uint32_t)hq[1] << 16);
        hv.y = (uint32_t)hq[2] | ((uint32_t)hq[3] << 16);
        hv.z = (uint32_t)hq[4] | ((uint32_t)hq[5] << 16);
        hv.w = (uint32_t)hq[6] | ((uint32_t)hq[7] << 16);
        lv.x = (uint32_t)lq[0] | ((uint32_t)lq[1] << 16);
        lv.y = (uint32_t)lq[2] | ((uint32_t)lq[3] << 16);
        lv.z = (uint32_t)lq[4] | ((uint32_t)lq[5] << 16);
        lv.w = (uint32_t)lq[6] | ((uint32_t)lq[7] << 16);
        uint4 rbh, rbl;
        if (t < 64) {
            size_t bi = (size_t)jrow * KD + ((size_t)kk << 8) + c0 + shalf*8;
            rbh = *(const uint4*)&g_woffBh[bi];
            rbl = *(const uint4*)&g_woffBl[bi];
        }

        __syncthreads();
        *(uint4*)&sAh[aSidx] = hv;
        *(uint4*)&sAl[aSidx] = lv;
        if (t < 64) {
            *(uint4*)&sBh[bSidx] = rbh;
            *(uint4*)&sBl[bSidx] = rbl;
        }
        __syncthreads();

        uint32_t ah[4], al[4], bh[4][2], bl[4][2];
        LDSM4(ah[0], ah[1], ah[2], ah[3], aHad);
        LDSM4(al[0], al[1], al[2], al[3], aLad);
        LDSM4(bh[0][0], bh[0][1], bh[1][0], bh[1][1], bHad);
        LDSM4(bh[2][0], bh[2][1], bh[3][0], bh[3][1], bHad + BSTEP16);
        LDSM4(bl[0][0], bl[0][1], bl[1][0], bl[1][1], bLad);
        LDSM4(bl[2][0], bl[2][1], bl[3][0], bl[3][1], bLad + BSTEP16);

        #pragma unroll
        for (int j = 0; j < 4; j++) {
            MMA_BF16(acc[j], ah, bh[j]);
            MMA_BF16(acc[j], ah, bl[j]);
            MMA_BF16(acc[j], al, bh[j]);
        }
    }

    // epilogue: partials to g_omp[g][p][32] (padded, no guards)
    int lr = lane >> 2, lc = (lane & 3) * 2;
    int mBase = wid*16 + lr;
    float* gout = g_omp + (size_t)g * NP * 32;
    #pragma unroll
    for (int j = 0; j < 4; j++) {
        int n = j*8 + lc;
        #pragma unroll
        for (int half = 0; half < 2; half++) {
            int m = mBase + half*8;
            int p = ((b*HH + h0 + (m >> 6))*WW + (m & 63));
            *(float2*)(gout + (size_t)p*32 + n) =
                make_float2(acc[j][half*2 + 0], acc[j][half*2 + 1]);
        }
    }
}

// ---------------- reduce partials + bias -> g_om ---------------------------
__global__ __launch_bounds__(256) void om_reduce_k(const float* __restrict__ boff) {
    int idx = blockIdx.x * 256 + threadIdx.x;
    if (idx >= NP*27) return;
    int p = idx / 27, j = idx - p*27;
    float v = g_omp[(size_t)p*32 + j]
            + g_omp[(size_t)(NP + p)*32 + j]
            + g_omp[(size_t)(2*NP + p)*32 + j]
            + boff[j];
    g_om[idx] = v;
}

// ---------------- bilinear sample + mask -> bf16 hi/lo im2col --------------
__global__ __launch_bounds__(256) void sample_k(const float* __restrict__ xh) {
    int wid = blockIdx.x * 8 + (threadIdx.x >> 5);
    int lane = threadIdx.x & 31;
    int p = wid / 9, k = wid - p*9;
    const float* omp = g_om + (size_t)p * 27;
    float dy = omp[2*k], dx = omp[2*k + 1];
    float mk = 1.f / (1.f + __expf(-omp[18 + k]));
    int b = p >> 12, hw = p & (HW - 1), h = hw >> 6, w = hw & 63;
    float ys = (float)(h + k/3 - 1) + dy;
    float xs = (float)(w + k%3 - 1) + dx;
    float y0f = floorf(ys), x0f = floorf(xs);
    float wy = ys - y0f, wx = xs - x0f;
    int y0 = (int)y0f, x0 = (int)x0f;
    int y1 = y0 + 1, x1 = x0 + 1;
    bool vy0 = ((unsigned)y0 < HH), vy1 = ((unsigned)y1 < HH);
    bool vx0 = ((unsigned)x0 < WW), vx1 = ((unsigned)x1 < WW);
    float w00 = (1.f - wy)*(1.f - wx)*mk;
    float w01 = (1.f - wy)*wx*mk;
    float w10 = wy*(1.f - wx)*mk;
    float w11 = wy*wx*mk;
    const float* base = xh + (size_t)b * HW * CHN;
    int c0 = lane * 8;
    const float4 z4 = make_float4(0.f, 0.f, 0.f, 0.f);
    float4 a00 = z4, b00 = z4, a01 = z4, b01 = z4;
    float4 a10 = z4, b10 = z4, a11 = z4, b11 = z4;
    if (vy0 && vx0) { const float4* q = (const float4*)(base + (size_t)(y0*WW + x0)*CHN + c0); a00 = q[0]; b00 = q[1]; }
    if (vy0 && vx1) { const float4* q = (const float4*)(base + (size_t)(y0*WW + x1)*CHN + c0); a01 = q[0]; b01 = q[1]; }
    if (vy1 && vx0) { const float4* q = (const float4*)(base + (size_t)(y1*WW + x0)*CHN + c0); a10 = q[0]; b10 = q[1]; }
    if (vy1 && vx1) { const float4* q = (const float4*)(base + (size_t)(y1*WW + x1)*CHN + c0); a11 = q[0]; b11 = q[1]; }
    float f[8];
    f[0] = w00*a00.x + w01*a01.x + w10*a10.x + w11*a11.x;
    f[1] = w00*a00.y + w01*a01.y + w10*a10.y + w11*a11.y;
    f[2] = w00*a00.z + w01*a01.z + w10*a10.z + w11*a11.z;
    f[3] = w00*a00.w + w01*a01.w + w10*a10.w + w11*a11.w;
    f[4] = w00*b00.x + w01*b01.x + w10*b10.x + w11*b11.x;
    f[5] = w00*b00.y + w01*b01.y + w10*b10.y + w11*b11.y;
    f[6] = w00*b00.z + w01*b01.z + w10*b10.z + w11*b11.z;
    f[7] = w00*b00.w + w01*b01.w + w10*b10.w + w11*b11.w;
    uint16_t hq[8], lq[8];
    #pragma unroll
    for (int q = 0; q < 8; q++) bf_split(f[q], hq[q], lq[q]);
    size_t idx = (size_t)wid*CHN + c0;
    uint4 hv, lv;
    hv.x = (uint32_t)hq[0] | ((uint32_t)hq[1] << 16);
    hv.y = (uint32_t)hq[2] | ((uint32_t)hq[3] << 16);
    hv.z = (uint32_t)hq[4] | ((uint32_t)hq[5] << 16);
    hv.w = (uint32_t)hq[6] | ((uint32_t)hq[7] << 16);
    lv.x = (uint32_t)lq[0] | ((uint32_t)lq[1] << 16);
    lv.y = (uint32_t)lq[2] | ((uint32_t)lq[3] << 16);
    lv.z = (uint32_t)lq[4] | ((uint32_t)lq[5] << 16);
    lv.w = (uint32_t)lq[6] | ((uint32_t)lq[7] << 16);
    *(uint4*)&g_colh[idx] = hv;
    *(uint4*)&g_coll[idx] = lv;
}

// ---------------- bf16x3 mma.sync GEMM + bias + ReLU -----------------------
// 3-stage cp.async pipeline; per-stage layout (bytes from stage base):
//   sAh @ 0, sAl @ 6144, sBh @ 12288, sBl @ 18432; stage stride 24576.
#define GSTAGE 24576
#define GSM_TOTAL (3*GSTAGE)
__global__ __launch_bounds__(256) void gemm_bf(const float* __restrict__ bias,
                                               float* __restrict__ Cout) {
    extern __shared__ __align__(16) uint16_t smg[];
    uint32_t sb = smem_u32(smg);

    int t = threadIdx.x;
    int wid = t >> 5, lane = t & 31;
    int n0 = blockIdx.x * 128;
    int m0 = blockIdx.y * 128;

    int srow = t >> 1, shalf = t & 1;
    const uint16_t* aH = g_colh + (size_t)(m0 + srow) * KD + shalf * 8;
    const uint16_t* aL = g_coll + (size_t)(m0 + srow) * KD + shalf * 8;
    const uint16_t* bH = g_wtBh + (size_t)(n0 + srow) * KD + shalf * 8;
    const uint16_t* bL = g_wtBl + (size_t)(n0 + srow) * KD + shalf * 8;
    uint32_t sOffB = (uint32_t)(srow * PADK + shalf * 8) * 2;   // byte offset in stage

    int sel = lane >> 3, r = lane & 7;
    uint32_t aOffB = (uint32_t)((((wid & 1) * 64) + (sel & 1) * 8 + r) * (PADK*2) + (sel >> 1) * 16);
    uint32_t bOffB = (uint32_t)((((wid >> 1) * 32) + (sel >> 1) * 8 + r) * (PADK*2) + (sel & 1) * 16);
    const int STEP16 = PADK * 16 * 2;

    float acc[4][4][4];
    #pragma unroll
    for (int i = 0; i < 4; i++)
        #pragma unroll
        for (int j = 0; j < 4; j++)
            #pragma unroll
            for (int q = 0; q < 4; q++) acc[i][j][q] = 0.f;

    // stage issue: kt-th K-chunk into stage s
    #define GSTAGE_ISSUE(kt, s) do { \
        uint32_t _b = sb + (uint32_t)(s) * GSTAGE + sOffB; \
        int _kc = (kt) * 16; \
        cp16(_b,          aH + _kc); \
        cp16(_b + 6144,   aL + _kc); \
        cp16(_b + 12288,  bH + _kc); \
        cp16(_b + 18432,  bL + _kc); \
    } while (0)

    GSTAGE_ISSUE(0, 0); CP_COMMIT();
    GSTAGE_ISSUE(1, 1); CP_COMMIT();

    const int NT = KD / 16;   // 144
    int s = 0;
    for (int kt = 0; kt < NT; kt++) {
        if (kt + 2 < NT) {
            int sn = s + 2; if (sn >= 3) sn -= 3;
            GSTAGE_ISSUE(kt + 2, sn);
        }
        CP_COMMIT();
        CP_WAIT2();
        __syncthreads();

        uint32_t base = sb + (uint32_t)s * GSTAGE;
        uint32_t aHad = base + aOffB;
        uint32_t aLad = base + 6144 + aOffB;
        uint32_t bHad = base + 12288 + bOffB;
        uint32_t bLad = base + 18432 + bOffB;

        uint32_t ah[4][4], al[4][4], bh[4][2], bl[4][2];
        #pragma unroll
        for (int i = 0; i < 4; i++) {
            LDSM4(ah[i][0], ah[i][1], ah[i][2], ah[i][3], aHad + i*STEP16);
            LDSM4(al[i][0], al[i][1], al[i][2], al[i][3], aLad + i*STEP16);
        }
        #pragma unroll
        for (int j = 0; j < 2; j++) {
            LDSM4(bh[2*j][0], bh[2*j][1], bh[2*j+1][0], bh[2*j+1][1], bHad + j*STEP16);
            LDSM4(bl[2*j][0], bl[2*j][1], bl[2*j+1][0], bl[2*j+1][1], bLad + j*STEP16);
        }

        #pragma unroll
        for (int i = 0; i < 4; i++)
            #pragma unroll
            for (int j = 0; j < 4; j++) {
                MMA_BF16(acc[i][j], ah[i], bh[j]);
                MMA_BF16(acc[i][j], ah[i], bl[j]);
                MMA_BF16(acc[i][j], al[i], bh[j]);
            }
        __syncthreads();
        s++; if (s >= 3) s = 0;
    }

    int lr = lane >> 2, lc = (lane & 3) * 2;
    int mBase = m0 + (wid & 1) * 64 + lr;
    int nBase = n0 + (wid >> 1) * 32 + lc;
    #pragma unroll
    for (int j = 0; j < 4; j++) {
        int n = nBase + j * 8;
        float b0 = bias[n], b1 = bias[n + 1];
        #pragma unroll
        for (int i = 0; i < 4; i++) {
            int m = mBase + i * 16;
            float2 v0, v1;
            v0.x = fmaxf(acc[i][j][0] + b0, 0.f);
            v0.y = fmaxf(acc[i][j][1] + b1, 0.f);
            v1.x = fmaxf(acc[i][j][2] + b0, 0.f);
            v1.y = fmaxf(acc[i][j][3] + b1, 0.f);
            *(float2*)(Cout + (size_t)m*CHN + n)       = v0;
            *(float2*)(Cout + (size_t)(m+8)*CHN + n)   = v1;
        }
    }
}

// ---------------- launcher ---------------------------------------------------
extern "C" void kernel_launch(void* const* d_in, const int* in_sizes, int n_in,
                              void* d_out, int out_size) {
    const float* x = (const float*)d_in[0];
    const float* woff[3] = {(const float*)d_in[1], (const float*)d_in[5], (const float*)d_in[9]};
    const float* boff[3] = {(const float*)d_in[2], (const float*)d_in[6], (const float*)d_in[10]};
    const float* wm[3]   = {(const float*)d_in[3], (const float*)d_in[7], (const float*)d_in[11]};
    const float* bm[3]   = {(const float*)d_in[4], (const float*)d_in[8], (const float*)d_in[12]};
    float* out = (float*)d_out;

    static int smem_set = 0;
    if (!smem_set) {
        cudaFuncSetAttribute(gemm_bf, cudaFuncAttributeMaxDynamicSharedMemorySize, GSM_TOTAL);
        smem_set = 1;
    }

    float *act0, *act1;
    cudaGetSymbolAddress((void**)&act0, g_act0);
    cudaGetSymbolAddress((void**)&act1, g_act1);
    float* bufs[2] = {act0, act1};

    dim3 tb(32, 8);
    transpose2d<<<dim3(HW/32, CHN/32, BB), tb>>>(x, act0, CHN, HW);

    for (int L = 0; L < 3; L++) {
        const float* src = bufs[L & 1];
        float* dst = bufs[(L & 1) ^ 1];
        woff_trans_k<<<(32*KD + 255)/256, 256>>>(woff[L]);
        wmain_trans_k<<<(CHN*KD + 255)/256, 256>>>(wm[L]);
        offset_conv_mma<<<dim3(128, 3), 256>>>(src);
        om_reduce_k<<<(NP*27 + 255)/256, 256>>>(boff[L]);
        sample_k<<<(NP*9)/8, 256>>>(src);
        gemm_bf<<<dim3(2, 128), 256, GSM_TOTAL>>>(bm[L], dst);
    }

    transpose2d<<<dim3(CHN/32, HW/32, BB), tb>>>(bufs[1], out, HW, CHN);
}

// round 14
// speedup vs baseline: 2.8782x; 1.0552x over previous
#include <cuda_runtime.h>
#include <cuda_bf16.h>
#include <math.h>
#include <stdint.h>

#define BB 4
#define CHN 256
#define HH 64
#define WW 64
#define HW (HH*WW)        // 4096
#define NP (BB*HW)        // 16384 pixels
#define K9 9
#define KD (CHN*K9)       // 2304

// ---------------- scratch (device globals: allocation-free) ----------------
__device__ float g_act0[NP*CHN];                 // NHWC activations ping (16 MB)
__device__ float g_act1[NP*CHN];                 // pong
__device__ float g_omp[(size_t)3*NP*32];         // offset-conv partials [g][p][32]
__device__ uint16_t g_xh[NP*CHN];                // layer input bf16 hi (8.4 MB)
__device__ uint16_t g_xl[NP*CHN];                // layer input bf16 lo
__device__ uint16_t g_colh[(size_t)NP*KD];       // im2col bf16 hi (75.5 MB)
__device__ uint16_t g_coll[(size_t)NP*KD];       // im2col bf16 lo
__device__ uint16_t g_wtBh[CHN*KD];              // weight B[o][k] bf16 hi
__device__ uint16_t g_wtBl[CHN*KD];              // weight B[o][k] bf16 lo
__device__ uint16_t g_woffBh[32*KD];             // offset weight B[j][k] bf16 hi (27 used)
__device__ uint16_t g_woffBl[32*KD];             // offset weight B[j][k] bf16 lo

// ---------------- helpers ----------------------------------------------------
__device__ __forceinline__ uint32_t smem_u32(const void* p) {
    uint32_t a;
    asm("{ .reg .u64 t; cvta.to.shared.u64 t, %1; cvt.u32.u64 %0, t; }" : "=r"(a) : "l"(p));
    return a;
}
__device__ __forceinline__ uint16_t f2bf(float v) {
    __nv_bfloat16 b = __float2bfloat16(v);
    return *reinterpret_cast<uint16_t*>(&b);
}
__device__ __forceinline__ float bf2f(uint16_t u) {
    __nv_bfloat16 b = *reinterpret_cast<__nv_bfloat16*>(&u);
    return __bfloat162float(b);
}
__device__ __forceinline__ void bf_split(float v, uint16_t& h, uint16_t& l) {
    h = f2bf(v);
    float r = v - bf2f(h);
    l = f2bf(r);
}
__device__ __forceinline__ void cp16(uint32_t dst, const void* src) {
    asm volatile("cp.async.cg.shared.global [%0], [%1], 16;" :: "r"(dst), "l"(src));
}
// predicated: zero-fill destination when !v (src-size 0)
__device__ __forceinline__ void cp16z(uint32_t dst, const void* src, bool v) {
    int sz = v ? 16 : 0;
    asm volatile("cp.async.cg.shared.global [%0], [%1], 16, %2;" :: "r"(dst), "l"(src), "r"(sz));
}
#define CP_COMMIT() asm volatile("cp.async.commit_group;" ::: "memory")
#define CP_WAIT2()  asm volatile("cp.async.wait_group 2;" ::: "memory")
#define CP_WAIT3()  asm volatile("cp.async.wait_group 3;" ::: "memory")

#define LDSM4(r0, r1, r2, r3, addr) \
    asm volatile("ldmatrix.sync.aligned.m8n8.x4.shared.b16 {%0,%1,%2,%3}, [%4];" \
        : "=r"(r0), "=r"(r1), "=r"(r2), "=r"(r3) : "r"(addr))

#define MMA_BF16(d, a, b) \
    asm volatile("mma.sync.aligned.m16n8k16.row.col.f32.bf16.bf16.f32 " \
        "{%0,%1,%2,%3}, {%4,%5,%6,%7}, {%8,%9}, {%0,%1,%2,%3};" \
        : "+f"((d)[0]), "+f"((d)[1]), "+f"((d)[2]), "+f"((d)[3]) \
        : "r"((a)[0]), "r"((a)[1]), "r"((a)[2]), "r"((a)[3]), "r"((b)[0]), "r"((b)[1]))

// ---------------- generic 2D transpose (per-batch via grid.z) --------------
__global__ void transpose2d(const float* __restrict__ in, float* __restrict__ out,
                            int rows, int cols) {
    __shared__ float tile[32][33];
    int z = blockIdx.z;
    const float* ip = in + (size_t)z * rows * cols;
    float* op = out + (size_t)z * rows * cols;
    int c0 = blockIdx.x * 32, r0 = blockIdx.y * 32;
    int x = c0 + threadIdx.x;
    for (int i = threadIdx.y; i < 32; i += 8) {
        int r = r0 + i;
        tile[i][threadIdx.x] = (r < rows && x < cols) ? ip[(size_t)r*cols + x] : 0.f;
    }
    __syncthreads();
    int xo = r0 + threadIdx.x;
    for (int i = threadIdx.y; i < 32; i += 8) {
        int c = c0 + i;
        if (c < cols && xo < rows) op[(size_t)c*rows + xo] = tile[threadIdx.x][i];
    }
}

// ---------------- input bf16 hi/lo split -----------------------------------
__global__ __launch_bounds__(256) void xsplit_k(const float* __restrict__ x) {
    int i = blockIdx.x * 256 + threadIdx.x;      // over NP*CHN/4
    float4 v = ((const float4*)x)[i];
    ushort4 h, l;
    bf_split(v.x, h.x, l.x); bf_split(v.y, h.y, l.y);
    bf_split(v.z, h.z, l.z); bf_split(v.w, h.w, l.w);
    ((ushort4*)g_xh)[i] = h;
    ((ushort4*)g_xl)[i] = l;
}

// ---------------- weight re-layouts ----------------------------------------
// g_woffBh/l[j*KD + kk*256 + c] = bf16 split of woff[(j*256+c)*9 + kk], j<27
__global__ void woff_trans_k(const float* __restrict__ woff) {
    int i = blockIdx.x * 256 + threadIdx.x;
    if (i >= 32*KD) return;
    int j = i / KD; int r = i - j*KD;
    int kk = r >> 8; int c = r & 255;
    float v = (j < 27) ? woff[(j*CHN + c)*9 + kk] : 0.f;
    uint16_t h, l;
    bf_split(v, h, l);
    g_woffBh[i] = h; g_woffBl[i] = l;
}

// g_wtBh/l[o*KD + kk*256 + c] = bf16 split of w[(o*256+c)*9 + kk]
__global__ void wmain_trans_k(const float* __restrict__ w) {
    int i = blockIdx.x * 256 + threadIdx.x;
    if (i >= CHN*KD) return;
    int o = i / KD; int r = i - o*KD;
    int kk = r >> 8; int c = r & 255;
    float v = w[((size_t)(o*CHN + c))*9 + kk];
    uint16_t h, l;
    bf_split(v, h, l);
    g_wtBh[i] = h; g_wtBl[i] = l;
}

// ---------------- offset conv: cp.async bf16x3 implicit GEMM ---------------
// K-split across 3 CTA groups (3 taps each). CTA = 128 px x 32 j, 48 k-iters.
// 3-stage pipeline; stage layout: Ah@0 (6144), Al@6144, Bh@12288 (1536), Bl@13824.
#define PADK 24   // bf16 elems per smem row (48B stride: conflict-free ldmatrix)
#define OSTAGE 15360
#define OSM_TOTAL (3*OSTAGE)
__global__ __launch_bounds__(256) void offset_conv_mma() {
    extern __shared__ __align__(16) uint16_t smo[];
    uint32_t osb = smem_u32(smo);

    int bid = blockIdx.x;               // 128 blocks
    int g = blockIdx.y;                 // tap group: taps 3g..3g+2
    int b = bid >> 5, h0 = (bid & 31) * 2;
    int t = threadIdx.x;
    int wid = t >> 5, lane = t & 31;

    int srow = t >> 1, shalf = t & 1;
    int row_ld = srow >> 6, w_ld = srow & 63;
    uint32_t sOffB = (uint32_t)(srow * PADK + shalf * 8) * 2;
    int jrow = t >> 1;                  // used when t<64
    uint32_t bStB = (uint32_t)(jrow * PADK + shalf * 8) * 2;

    int sel = lane >> 3, r8 = lane & 7;
    uint32_t aOffB = (uint32_t)((wid*16 + (sel & 1)*8 + r8) * (PADK*2) + (sel >> 1) * 16);
    uint32_t bOffB = (uint32_t)(((sel >> 1)*8 + r8) * (PADK*2) + (sel & 1) * 16);
    const int BSTEP16 = PADK * 16 * 2;

    float acc[4][4];
    #pragma unroll
    for (int j = 0; j < 4; j++)
        #pragma unroll
        for (int q = 0; q < 4; q++) acc[j][q] = 0.f;

    #define OSTAGE_ISSUE(kt, s) do { \
        int _kk = g*3 + ((kt) >> 4), _c0 = ((kt) & 15) << 4; \
        int _rr = _kk / 3, _ss = _kk - _rr*3; \
        int _hy = h0 + row_ld + _rr - 1, _wx = w_ld + _ss - 1; \
        bool _v = ((unsigned)_hy < (unsigned)HH) && ((unsigned)_wx < (unsigned)WW); \
        size_t _off = _v ? ((size_t)((b*HH + _hy)*WW + _wx))*CHN + _c0 + shalf*8 : 0; \
        uint32_t _sb = osb + (uint32_t)(s) * OSTAGE; \
        cp16z(_sb + sOffB,        g_xh + _off, _v); \
        cp16z(_sb + 6144 + sOffB, g_xl + _off, _v); \
        if (t < 64) { \
            size_t _bi = (size_t)jrow * KD + ((size_t)_kk << 8) + _c0 + shalf*8; \
            cp16(_sb + 12288 + bStB, g_woffBh + _bi); \
            cp16(_sb + 13824 + bStB, g_woffBl + _bi); \
        } \
    } while (0)

    OSTAGE_ISSUE(0, 0); CP_COMMIT();
    OSTAGE_ISSUE(1, 1); CP_COMMIT();

    int s = 0;
    for (int kt = 0; kt < 48; kt++) {
        if (kt + 2 < 48) {
            int sn = s + 2; if (sn >= 3) sn -= 3;
            OSTAGE_ISSUE(kt + 2, sn);
        }
        CP_COMMIT();
        CP_WAIT2();
        __syncthreads();

        uint32_t base = osb + (uint32_t)s * OSTAGE;
        uint32_t aHad = base + aOffB;
        uint32_t aLad = base + 6144 + aOffB;
        uint32_t bHad = base + 12288 + bOffB;
        uint32_t bLad = base + 13824 + bOffB;

        uint32_t ah[4], al[4], bh[4][2], bl[4][2];
        LDSM4(ah[0], ah[1], ah[2], ah[3], aHad);
        LDSM4(al[0], al[1], al[2], al[3], aLad);
        LDSM4(bh[0][0], bh[0][1], bh[1][0], bh[1][1], bHad);
        LDSM4(bh[2][0], bh[2][1], bh[3][0], bh[3][1], bHad + BSTEP16);
        LDSM4(bl[0][0], bl[0][1], bl[1][0], bl[1][1], bLad);
        LDSM4(bl[2][0], bl[2][1], bl[3][0], bl[3][1], bLad + BSTEP16);

        #pragma unroll
        for (int j = 0; j < 4; j++) {
            MMA_BF16(acc[j], ah, bh[j]);
            MMA_BF16(acc[j], ah, bl[j]);
            MMA_BF16(acc[j], al, bh[j]);
        }
        __syncthreads();
        s++; if (s >= 3) s = 0;
    }

    // epilogue: partials to g_omp[g][p][32] (padded, no guards)
    int lr = lane >> 2, lc = (lane & 3) * 2;
    int mBase = wid*16 + lr;
    float* gout = g_omp + (size_t)g * NP * 32;
    #pragma unroll
    for (int j = 0; j < 4; j++) {
        int n = j*8 + lc;
        #pragma unroll
        for (int half = 0; half < 2; half++) {
            int m = mBase + half*8;
            int p = ((b*HH + h0 + (m >> 6))*WW + (m & 63));
            *(float2*)(gout + (size_t)p*32 + n) =
                make_float2(acc[j][half*2 + 0], acc[j][half*2 + 1]);
        }
    }
}

// ---------------- bilinear sample + mask -> bf16 hi/lo im2col --------------
// reads offset-conv partials directly (reduce fused here)
__global__ __launch_bounds__(256) void sample_k(const float* __restrict__ xh,
                                                const float* __restrict__ boff) {
    int wid = blockIdx.x * 8 + (threadIdx.x >> 5);
    int lane = threadIdx.x & 31;
    int p = wid / 9, k = wid - p*9;
    const float* s0 = g_omp + (size_t)p * 32;
    const float* s1 = g_omp + (size_t)(NP + p) * 32;
    const float* s2 = g_omp + (size_t)(2*NP + p) * 32;
    float dy = s0[2*k]   + s1[2*k]   + s2[2*k]   + boff[2*k];
    float dx = s0[2*k+1] + s1[2*k+1] + s2[2*k+1] + boff[2*k+1];
    float ml = s0[18+k]  + s1[18+k]  + s2[18+k]  + boff[18+k];
    float mk = 1.f / (1.f + __expf(-ml));
    int b = p >> 12, hw = p & (HW - 1), h = hw >> 6, w = hw & 63;
    float ys = (float)(h + k/3 - 1) + dy;
    float xs = (float)(w + k%3 - 1) + dx;
    float y0f = floorf(ys), x0f = floorf(xs);
    float wy = ys - y0f, wx = xs - x0f;
    int y0 = (int)y0f, x0 = (int)x0f;
    int y1 = y0 + 1, x1 = x0 + 1;
    bool vy0 = ((unsigned)y0 < HH), vy1 = ((unsigned)y1 < HH);
    bool vx0 = ((unsigned)x0 < WW), vx1 = ((unsigned)x1 < WW);
    float w00 = (1.f - wy)*(1.f - wx)*mk;
    float w01 = (1.f - wy)*wx*mk;
    float w10 = wy*(1.f - wx)*mk;
    float w11 = wy*wx*mk;
    const float* base = xh + (size_t)b * HW * CHN;
    int c0 = lane * 8;
    const float4 z4 = make_float4(0.f, 0.f, 0.f, 0.f);
    float4 a00 = z4, b00 = z4, a01 = z4, b01 = z4;
    float4 a10 = z4, b10 = z4, a11 = z4, b11 = z4;
    if (vy0 && vx0) { const float4* q = (const float4*)(base + (size_t)(y0*WW + x0)*CHN + c0); a00 = q[0]; b00 = q[1]; }
    if (vy0 && vx1) { const float4* q = (const float4*)(base + (size_t)(y0*WW + x1)*CHN + c0); a01 = q[0]; b01 = q[1]; }
    if (vy1 && vx0) { const float4* q = (const float4*)(base + (size_t)(y1*WW + x0)*CHN + c0); a10 = q[0]; b10 = q[1]; }
    if (vy1 && vx1) { const float4* q = (const float4*)(base + (size_t)(y1*WW + x1)*CHN + c0); a11 = q[0]; b11 = q[1]; }
    float f[8];
    f[0] = w00*a00.x + w01*a01.x + w10*a10.x + w11*a11.x;
    f[1] = w00*a00.y + w01*a01.y + w10*a10.y + w11*a11.y;
    f[2] = w00*a00.z + w01*a01.z + w10*a10.z + w11*a11.z;
    f[3] = w00*a00.w + w01*a01.w + w10*a10.w + w11*a11.w;
    f[4] = w00*b00.x + w01*b01.x + w10*b10.x + w11*b11.x;
    f[5] = w00*b00.y + w01*b01.y + w10*b10.y + w11*b11.y;
    f[6] = w00*b00.z + w01*b01.z + w10*b10.z + w11*b11.z;
    f[7] = w00*b00.w + w01*b01.w + w10*b10.w + w11*b11.w;
    uint16_t hq[8], lq[8];
    #pragma unroll
    for (int q = 0; q < 8; q++) bf_split(f[q], hq[q], lq[q]);
    size_t idx = (size_t)wid*CHN + c0;
    uint4 hv, lv;
    hv.x = (uint32_t)hq[0] | ((uint32_t)hq[1] << 16);
    hv.y = (uint32_t)hq[2] | ((uint32_t)hq[3] << 16);
    hv.z = (uint32_t)hq[4] | ((uint32_t)hq[5] << 16);
    hv.w = (uint32_t)hq[6] | ((uint32_t)hq[7] << 16);
    lv.x = (uint32_t)lq[0] | ((uint32_t)lq[1] << 16);
    lv.y = (uint32_t)lq[2] | ((uint32_t)lq[3] << 16);
    lv.z = (uint32_t)lq[4] | ((uint32_t)lq[5] << 16);
    lv.w = (uint32_t)lq[6] | ((uint32_t)lq[7] << 16);
    *(uint4*)&g_colh[idx] = hv;
    *(uint4*)&g_coll[idx] = lv;
}

// ---------------- bf16x3 mma.sync GEMM + bias + ReLU -----------------------
// 4-stage cp.async pipeline; per-stage layout (bytes from stage base):
//   sAh @ 0, sAl @ 6144, sBh @ 12288, sBl @ 18432; stage stride 24576.
#define GSTAGE 24576
#define GSM_TOTAL (4*GSTAGE)
__global__ __launch_bounds__(256) void gemm_bf(const float* __restrict__ bias,
                                               float* __restrict__ Cout) {
    extern __shared__ __align__(16) uint16_t smg[];
    uint32_t sb = smem_u32(smg);

    int t = threadIdx.x;
    int wid = t >> 5, lane = t & 31;
    int n0 = blockIdx.x * 128;
    int m0 = blockIdx.y * 128;

    int srow = t >> 1, shalf = t & 1;
    const uint16_t* aH = g_colh + (size_t)(m0 + srow) * KD + shalf * 8;
    const uint16_t* aL = g_coll + (size_t)(m0 + srow) * KD + shalf * 8;
    const uint16_t* bH = g_wtBh + (size_t)(n0 + srow) * KD + shalf * 8;
    const uint16_t* bL = g_wtBl + (size_t)(n0 + srow) * KD + shalf * 8;
    uint32_t sOffB = (uint32_t)(srow * PADK + shalf * 8) * 2;   // byte offset in stage

    int sel = lane >> 3, r = lane & 7;
    uint32_t aOffB = (uint32_t)((((wid & 1) * 64) + (sel & 1) * 8 + r) * (PADK*2) + (sel >> 1) * 16);
    uint32_t bOffB = (uint32_t)((((wid >> 1) * 32) + (sel >> 1) * 8 + r) * (PADK*2) + (sel & 1) * 16);
    const int STEP16 = PADK * 16 * 2;

    float acc[4][4][4];
    #pragma unroll
    for (int i = 0; i < 4; i++)
        #pragma unroll
        for (int j = 0; j < 4; j++)
            #pragma unroll
            for (int q = 0; q < 4; q++) acc[i][j][q] = 0.f;

    #define GSTAGE_ISSUE(kt, s) do { \
        uint32_t _b = sb + (uint32_t)(s) * GSTAGE + sOffB; \
        int _kc = (kt) * 16; \
        cp16(_b,          aH + _kc); \
        cp16(_b + 6144,   aL + _kc); \
        cp16(_b + 12288,  bH + _kc); \
        cp16(_b + 18432,  bL + _kc); \
    } while (0)

    GSTAGE_ISSUE(0, 0); CP_COMMIT();
    GSTAGE_ISSUE(1, 1); CP_COMMIT();
    GSTAGE_ISSUE(2, 2); CP_COMMIT();

    const int NT = KD / 16;   // 144
    int s = 0;
    for (int kt = 0; kt < NT; kt++) {
        if (kt + 3 < NT) {
            int sn = s + 3; if (sn >= 4) sn -= 4;
            GSTAGE_ISSUE(kt + 3, sn);
        }
        CP_COMMIT();
        CP_WAIT3();
        __syncthreads();

        uint32_t base = sb + (uint32_t)s * GSTAGE;
        uint32_t aHad = base + aOffB;
        uint32_t aLad = base + 6144 + aOffB;
        uint32_t bHad = base + 12288 + bOffB;
        uint32_t bLad = base + 18432 + bOffB;

        uint32_t ah[4][4], al[4][4], bh[4][2], bl[4][2];
        #pragma unroll
        for (int i = 0; i < 4; i++) {
            LDSM4(ah[i][0], ah[i][1], ah[i][2], ah[i][3], aHad + i*STEP16);
            LDSM4(al[i][0], al[i][1], al[i][2], al[i][3], aLad + i*STEP16);
        }
        #pragma unroll
        for (int j = 0; j < 2; j++) {
            LDSM4(bh[2*j][0], bh[2*j][1], bh[2*j+1][0], bh[2*j+1][1], bHad + j*STEP16);
            LDSM4(bl[2*j][0], bl[2*j][1], bl[2*j+1][0], bl[2*j+1][1], bLad + j*STEP16);
        }

        #pragma unroll
        for (int i = 0; i < 4; i++)
            #pragma unroll
            for (int j = 0; j < 4; j++) {
                MMA_BF16(acc[i][j], ah[i], bh[j]);
                MMA_BF16(acc[i][j], ah[i], bl[j]);
                MMA_BF16(acc[i][j], al[i], bh[j]);
            }
        __syncthreads();
        s++; if (s >= 4) s = 0;
    }

    int lr = lane >> 2, lc = (lane & 3) * 2;
    int mBase = m0 + (wid & 1) * 64 + lr;
    int nBase = n0 + (wid >> 1) * 32 + lc;
    #pragma unroll
    for (int j = 0; j < 4; j++) {
        int n = nBase + j * 8;
        float b0 = bias[n], b1 = bias[n + 1];
        #pragma unroll
        for (int i = 0; i < 4; i++) {
            int m = mBase + i * 16;
            float2 v0, v1;
            v0.x = fmaxf(acc[i][j][0] + b0, 0.f);
            v0.y = fmaxf(acc[i][j][1] + b1, 0.f);
            v1.x = fmaxf(acc[i][j][2] + b0, 0.f);
            v1.y = fmaxf(acc[i][j][3] + b1, 0.f);
            *(float2*)(Cout + (size_t)m*CHN + n)       = v0;
            *(float2*)(Cout + (size_t)(m+8)*CHN + n)   = v1;
        }
    }
}

// ---------------- launcher ---------------------------------------------------
extern "C" void kernel_launch(void* const* d_in, const int* in_sizes, int n_in,
                              void* d_out, int out_size) {
    const float* x = (const float*)d_in[0];
    const float* woff[3] = {(const float*)d_in[1], (const float*)d_in[5], (const float*)d_in[9]};
    const float* boff[3] = {(const float*)d_in[2], (const float*)d_in[6], (const float*)d_in[10]};
    const float* wm[3]   = {(const float*)d_in[3], (const float*)d_in[7], (const float*)d_in[11]};
    const float* bm[3]   = {(const float*)d_in[4], (const float*)d_in[8], (const float*)d_in[12]};
    float* out = (float*)d_out;

    static int smem_set = 0;
    if (!smem_set) {
        cudaFuncSetAttribute(gemm_bf, cudaFuncAttributeMaxDynamicSharedMemorySize, GSM_TOTAL);
        cudaFuncSetAttribute(offset_conv_mma, cudaFuncAttributeMaxDynamicSharedMemorySize, OSM_TOTAL);
        smem_set = 1;
    }

    float *act0, *act1;
    cudaGetSymbolAddress((void**)&act0, g_act0);
    cudaGetSymbolAddress((void**)&act1, g_act1);
    float* bufs[2] = {act0, act1};

    dim3 tb(32, 8);
    transpose2d<<<dim3(HW/32, CHN/32, BB), tb>>>(x, act0, CHN, HW);

    for (int L = 0; L < 3; L++) {
        const float* src = bufs[L & 1];
        float* dst = bufs[(L & 1) ^ 1];
        woff_trans_k<<<(32*KD + 255)/256, 256>>>(woff[L]);
        wmain_trans_k<<<(CHN*KD + 255)/256, 256>>>(wm[L]);
        xsplit_k<<<(NP*CHN/4 + 255)/256, 256>>>(src);
        offset_conv_mma<<<dim3(128, 3), 256, OSM_TOTAL>>>();
        sample_k<<<(NP*9)/8, 256>>>(src, boff[L]);
        gemm_bf<<<dim3(2, 128), 256, GSM_TOTAL>>>(bm[L], dst);
    }

    transpose2d<<<dim3(CHN/32, HW/32, BB), tb>>>(bufs[1], out, HW, CHN);
}